// round 1
// baseline (speedup 1.0000x reference)
#include <cuda_runtime.h>
#include <math.h>

// Problem constants
#define BB_   2
#define SS_   2048
#define HID_  1024
#define NH_   16
#define HD_   64
#define FF_   4096
#define TOK_  (BB_*SS_)   // 4096

// ---------------- scratch (static __device__ — allocation-free) ----------------
__device__ float g_h  [TOK_*HID_];
__device__ float g_q  [TOK_*HID_];
__device__ float g_k  [TOK_*HID_];
__device__ float g_v  [TOK_*HID_];
__device__ float g_sc [BB_*NH_*SS_*SS_];   // 134,217,728 floats = 512 MB
__device__ float g_ctx[TOK_*HID_];
__device__ float g_x2 [TOK_*HID_];
__device__ float g_h2 [TOK_*HID_];
__device__ float g_ff [TOK_*FF_];

// ---------------- block reductions (256 threads) ----------------
template<bool MAX>
__device__ __forceinline__ float block_reduce_256(float v) {
    __shared__ float sh[8];
    int lane = threadIdx.x & 31, w = threadIdx.x >> 5;
    #pragma unroll
    for (int o = 16; o; o >>= 1) {
        float u = __shfl_xor_sync(0xffffffffu, v, o);
        v = MAX ? fmaxf(v, u) : v + u;
    }
    if (lane == 0) sh[w] = v;
    __syncthreads();
    if (w == 0) {
        v = sh[lane & 7];
        #pragma unroll
        for (int o = 4; o; o >>= 1) {
            float u = __shfl_xor_sync(0xffffffffu, v, o);
            v = MAX ? fmaxf(v, u) : v + u;
        }
        if (lane == 0) sh[0] = v;
    }
    __syncthreads();
    float r = sh[0];
    __syncthreads();
    return r;
}

// ---------------- LayerNorm: one block per token row of 1024 ----------------
__global__ void ln_kernel(const float* __restrict__ x, const float* __restrict__ g,
                          const float* __restrict__ beta, float* __restrict__ out) {
    size_t base = (size_t)blockIdx.x * HID_;
    const float4* xp = reinterpret_cast<const float4*>(x + base);
    int t = threadIdx.x;
    float4 v = xp[t];
    float s = v.x + v.y + v.z + v.w;
    s = block_reduce_256<false>(s);
    float mean = s * (1.0f / HID_);
    float dx = v.x - mean, dy = v.y - mean, dz = v.z - mean, dw = v.w - mean;
    float q = dx*dx + dy*dy + dz*dz + dw*dw;
    q = block_reduce_256<false>(q);
    float r = rsqrtf(q * (1.0f / HID_) + 1e-5f);
    float4 gv = reinterpret_cast<const float4*>(g)[t];
    float4 bv = reinterpret_cast<const float4*>(beta)[t];
    float4 o;
    o.x = dx * r * gv.x + bv.x;
    o.y = dy * r * gv.y + bv.y;
    o.z = dz * r * gv.z + bv.z;
    o.w = dw * r * gv.w + bv.w;
    reinterpret_cast<float4*>(out + base)[t] = o;
}

// ---------------- softmax over rows of 2048 ----------------
__global__ void softmax_kernel(float* __restrict__ s) {
    size_t base = (size_t)blockIdx.x * SS_;
    float4* p = reinterpret_cast<float4*>(s + base);
    int t = threadIdx.x;
    float4 a = p[t], b = p[t + 256];
    float m = fmaxf(fmaxf(fmaxf(a.x, a.y), fmaxf(a.z, a.w)),
                    fmaxf(fmaxf(b.x, b.y), fmaxf(b.z, b.w)));
    m = block_reduce_256<true>(m);
    a.x = expf(a.x - m); a.y = expf(a.y - m); a.z = expf(a.z - m); a.w = expf(a.w - m);
    b.x = expf(b.x - m); b.y = expf(b.y - m); b.z = expf(b.z - m); b.w = expf(b.w - m);
    float sum = a.x + a.y + a.z + a.w + b.x + b.y + b.z + b.w;
    sum = block_reduce_256<false>(sum);
    float inv = 1.0f / sum;
    a.x *= inv; a.y *= inv; a.z *= inv; a.w *= inv;
    b.x *= inv; b.y *= inv; b.z *= inv; b.w *= inv;
    p[t] = a; p[t + 256] = b;
}

// ---------------- generic tiled SGEMM ----------------
// C[M,N] = A[M,K] @ op(B) (+ epilogue)
//   BT=false: B is [N,K] row-major (weights, x @ W^T)
//   BT=true : B is [K,N] row-major (attn @ V)
// EPI: 0 = +bias (bias may be null)
//      1 = *scale + (mask[col]-1)*10000   (attention scores)
//      2 = gelu(acc + bias)               (exact, erf-based)
//      3 = acc + bias + residual
// Batched over grid.z; per-z offset = (z/16)*s?b + (z%16)*s?h  (batch/head decomposition).
// All M,N multiples of 64; K multiple of 16.
template<bool BT, int EPI>
__global__ __launch_bounds__(256) void gemm_kernel(
    int M, int N, int K,
    const float* __restrict__ A,  int lda, long long sAb, long long sAh,
    const float* __restrict__ Bm, int ldb, long long sBb, long long sBh,
    float* __restrict__ C,        int ldc, long long sCb, long long sCh,
    const float* __restrict__ bias,
    const float* __restrict__ residual,
    const float* __restrict__ mask,
    float scale)
{
    __shared__ float As[16][68];
    __shared__ float Bs[16][68];

    const int bz = blockIdx.z;
    const int bb = bz >> 4;
    const int hh = bz & 15;
    A  += bb * sAb + hh * sAh;
    Bm += bb * sBb + hh * sBh;
    C  += bb * sCb + hh * sCh;

    const int tid = threadIdx.x;
    const int tx = tid & 15, ty = tid >> 4;
    const int row0 = blockIdx.y * 64;
    const int col0 = blockIdx.x * 64;

    const int lr = tid >> 2;          // 0..63  (row within tile for A/B loads)
    const int lk = (tid & 3) * 4;     // 0,4,8,12
    const int bk = tid >> 4;          // 0..15  (BT path)
    const int bn = (tid & 15) * 4;    // 0..60

    float acc[4][4] = {};

    for (int k0 = 0; k0 < K; k0 += 16) {
        float4 av = *reinterpret_cast<const float4*>(&A[(size_t)(row0 + lr) * lda + k0 + lk]);
        As[lk + 0][lr] = av.x; As[lk + 1][lr] = av.y;
        As[lk + 2][lr] = av.z; As[lk + 3][lr] = av.w;
        if (!BT) {
            float4 bv = *reinterpret_cast<const float4*>(&Bm[(size_t)(col0 + lr) * ldb + k0 + lk]);
            Bs[lk + 0][lr] = bv.x; Bs[lk + 1][lr] = bv.y;
            Bs[lk + 2][lr] = bv.z; Bs[lk + 3][lr] = bv.w;
        } else {
            float4 bv = *reinterpret_cast<const float4*>(&Bm[(size_t)(k0 + bk) * ldb + col0 + bn]);
            *reinterpret_cast<float4*>(&Bs[bk][bn]) = bv;
        }
        __syncthreads();
        #pragma unroll
        for (int kk = 0; kk < 16; kk++) {
            float4 a4 = *reinterpret_cast<const float4*>(&As[kk][ty * 4]);
            float4 b4 = *reinterpret_cast<const float4*>(&Bs[kk][tx * 4]);
            float ar[4] = {a4.x, a4.y, a4.z, a4.w};
            float br[4] = {b4.x, b4.y, b4.z, b4.w};
            #pragma unroll
            for (int i = 0; i < 4; i++)
                #pragma unroll
                for (int j = 0; j < 4; j++)
                    acc[i][j] = fmaf(ar[i], br[j], acc[i][j]);
        }
        __syncthreads();
    }

    float badd[4];
    #pragma unroll
    for (int j = 0; j < 4; j++) {
        int c = col0 + tx * 4 + j;
        if (EPI == 1) badd[j] = (mask[bb * N + c] - 1.0f) * 10000.0f;
        else          badd[j] = bias ? bias[c] : 0.0f;
    }

    #pragma unroll
    for (int i = 0; i < 4; i++) {
        int r = row0 + ty * 4 + i;
        float vv[4];
        #pragma unroll
        for (int j = 0; j < 4; j++) {
            float v = acc[i][j];
            if (EPI == 1) v = v * scale + badd[j];
            else          v = v + badd[j];
            if (EPI == 2) v = 0.5f * v * (1.0f + erff(v * 0.70710678118654752f));
            if (EPI == 3) v += residual[(size_t)r * ldc + col0 + tx * 4 + j];
            vv[j] = v;
        }
        float4 o; o.x = vv[0]; o.y = vv[1]; o.z = vv[2]; o.w = vv[3];
        *reinterpret_cast<float4*>(&C[(size_t)r * ldc + col0 + tx * 4]) = o;
    }
}

// ---------------- launch ----------------
extern "C" void kernel_launch(void* const* d_in, const int* in_sizes, int n_in,
                              void* d_out, int out_size) {
    const float* x   = (const float*)d_in[0];
    const float* am  = (const float*)d_in[1];
    const float* Wq  = (const float*)d_in[2];
    const float* bq  = (const float*)d_in[3];
    const float* Wk  = (const float*)d_in[4];
    const float* bk  = (const float*)d_in[5];
    const float* Wv  = (const float*)d_in[6];
    const float* bv  = (const float*)d_in[7];
    const float* Wo  = (const float*)d_in[8];
    const float* bo  = (const float*)d_in[9];
    const float* W1  = (const float*)d_in[10];
    const float* b1  = (const float*)d_in[11];
    const float* W2  = (const float*)d_in[12];
    const float* b2  = (const float*)d_in[13];
    const float* g1  = (const float*)d_in[14];
    const float* be1 = (const float*)d_in[15];
    const float* g2  = (const float*)d_in[16];
    const float* be2 = (const float*)d_in[17];
    float* out = (float*)d_out;

    float *h, *q, *k, *v, *sc, *ctx, *x2, *h2, *ff;
    cudaGetSymbolAddress((void**)&h,   g_h);
    cudaGetSymbolAddress((void**)&q,   g_q);
    cudaGetSymbolAddress((void**)&k,   g_k);
    cudaGetSymbolAddress((void**)&v,   g_v);
    cudaGetSymbolAddress((void**)&sc,  g_sc);
    cudaGetSymbolAddress((void**)&ctx, g_ctx);
    cudaGetSymbolAddress((void**)&x2,  g_x2);
    cudaGetSymbolAddress((void**)&h2,  g_h2);
    cudaGetSymbolAddress((void**)&ff,  g_ff);

    const long long sQb = (long long)SS_ * HID_;   // batch stride into q/k/v/ctx
    const long long sQh = HD_;                     // head stride
    const long long sSb = (long long)NH_ * SS_ * SS_;
    const long long sSh = (long long)SS_ * SS_;

    dim3 blk(256);

    // h = LN1(x)
    ln_kernel<<<TOK_, blk>>>(x, g1, be1, h);

    // q/k/v = h @ W^T + b
    gemm_kernel<false,0><<<dim3(HID_/64, TOK_/64, 1), blk>>>(TOK_, HID_, HID_,
        h, HID_, 0, 0,  Wq, HID_, 0, 0,  q, HID_, 0, 0,  bq, nullptr, nullptr, 0.f);
    gemm_kernel<false,0><<<dim3(HID_/64, TOK_/64, 1), blk>>>(TOK_, HID_, HID_,
        h, HID_, 0, 0,  Wk, HID_, 0, 0,  k, HID_, 0, 0,  bk, nullptr, nullptr, 0.f);
    gemm_kernel<false,0><<<dim3(HID_/64, TOK_/64, 1), blk>>>(TOK_, HID_, HID_,
        h, HID_, 0, 0,  Wv, HID_, 0, 0,  v, HID_, 0, 0,  bv, nullptr, nullptr, 0.f);

    // scores[b,h] = q @ k^T / 8 + (mask-1)*1e4
    gemm_kernel<false,1><<<dim3(SS_/64, SS_/64, BB_*NH_), blk>>>(SS_, SS_, HD_,
        q, HID_, sQb, sQh,  k, HID_, sQb, sQh,  sc, SS_, sSb, sSh,
        nullptr, nullptr, am, 0.125f);

    // softmax rows
    softmax_kernel<<<BB_*NH_*SS_, blk>>>(sc);

    // ctx[b,h] = attn @ v   (B is [K,N] = v^T view)
    gemm_kernel<true,0><<<dim3(HD_/64, SS_/64, BB_*NH_), blk>>>(SS_, HD_, SS_,
        sc, SS_, sSb, sSh,  v, HID_, sQb, sQh,  ctx, HID_, sQb, sQh,
        nullptr, nullptr, nullptr, 0.f);

    // x2 = x + ctx @ Wo^T + bo
    gemm_kernel<false,3><<<dim3(HID_/64, TOK_/64, 1), blk>>>(TOK_, HID_, HID_,
        ctx, HID_, 0, 0,  Wo, HID_, 0, 0,  x2, HID_, 0, 0,  bo, x, nullptr, 0.f);

    // h2 = LN2(x2)
    ln_kernel<<<TOK_, blk>>>(x2, g2, be2, h2);

    // ff = gelu(h2 @ W1^T + b1)
    gemm_kernel<false,2><<<dim3(FF_/64, TOK_/64, 1), blk>>>(TOK_, FF_, HID_,
        h2, HID_, 0, 0,  W1, HID_, 0, 0,  ff, FF_, 0, 0,  b1, nullptr, nullptr, 0.f);

    // out = x2 + ff @ W2^T + b2
    gemm_kernel<false,3><<<dim3(HID_/64, TOK_/64, 1), blk>>>(TOK_, HID_, FF_,
        ff, FF_, 0, 0,  W2, FF_, 0, 0,  out, HID_, 0, 0,  b2, x2, nullptr, 0.f);
}

// round 3
// speedup vs baseline: 3.2422x; 3.2422x over previous
#include <cuda_runtime.h>
#include <math.h>
#include <stdint.h>

#define BB_   2
#define SS_   2048
#define HID_  1024
#define NH_   16
#define HD_   64
#define FF_   4096
#define TOK_  (BB_*SS_)   // 4096

// ---------------- scratch ----------------
__device__ float g_h  [TOK_*HID_];
__device__ float g_q  [TOK_*HID_];
__device__ float g_k  [TOK_*HID_];
__device__ float g_v  [TOK_*HID_];
__device__ float g_vt [TOK_*HID_];                 // [B,H,64,S]
__device__ float g_sc [(size_t)BB_*NH_*SS_*SS_];   // 512 MB
__device__ float g_ctx[TOK_*HID_];
__device__ float g_x2 [TOK_*HID_];
__device__ float g_h2 [TOK_*HID_];
__device__ float g_ff [TOK_*FF_];
__device__ float g_wr [12*1024*1024];              // tf32-rounded weights

// ---------------- helpers ----------------
__device__ __forceinline__ float tf32r(float x) {
    float y;
    asm("cvt.rna.tf32.f32 %0, %1;" : "=f"(y) : "f"(x));
    return y;
}
__device__ __forceinline__ uint32_t smem_u32(const void* p) {
    uint32_t a;
    asm("{ .reg .u64 t; cvta.to.shared.u64 t, %1; cvt.u32.u64 %0, t; }" : "=r"(a) : "l"(p));
    return a;
}
#define CP16(dst, src) \
    asm volatile("cp.async.cg.shared.global [%0], [%1], 16;" :: "r"(dst), "l"(src) : "memory")
#define CP_COMMIT() asm volatile("cp.async.commit_group;" ::: "memory")
#define CP_WAIT1()  asm volatile("cp.async.wait_group 1;" ::: "memory")
#define CP_WAIT0()  asm volatile("cp.async.wait_group 0;" ::: "memory")

__device__ __forceinline__ void mma1688(float* c, const uint32_t* a, uint32_t b0, uint32_t b1) {
    asm volatile(
        "mma.sync.aligned.m16n8k8.row.col.f32.tf32.tf32.f32 "
        "{%0,%1,%2,%3}, {%4,%5,%6,%7}, {%8,%9}, {%0,%1,%2,%3};"
        : "+f"(c[0]), "+f"(c[1]), "+f"(c[2]), "+f"(c[3])
        : "r"(a[0]), "r"(a[1]), "r"(a[2]), "r"(a[3]), "r"(b0), "r"(b1));
}

// ---------------- elementwise tf32 round ----------------
__global__ void round_kernel(const float* __restrict__ src, float* __restrict__ dst, int n4) {
    int i = blockIdx.x * blockDim.x + threadIdx.x;
    if (i < n4) {
        float4 v = reinterpret_cast<const float4*>(src)[i];
        v.x = tf32r(v.x); v.y = tf32r(v.y); v.z = tf32r(v.z); v.w = tf32r(v.w);
        reinterpret_cast<float4*>(dst)[i] = v;
    }
}

// ---------------- block reduction ----------------
template<bool MAX>
__device__ __forceinline__ float block_reduce_256(float v) {
    __shared__ float sh[8];
    int lane = threadIdx.x & 31, w = threadIdx.x >> 5;
    #pragma unroll
    for (int o = 16; o; o >>= 1) {
        float u = __shfl_xor_sync(0xffffffffu, v, o);
        v = MAX ? fmaxf(v, u) : v + u;
    }
    if (lane == 0) sh[w] = v;
    __syncthreads();
    if (w == 0) {
        v = sh[lane & 7];
        #pragma unroll
        for (int o = 4; o; o >>= 1) {
            float u = __shfl_xor_sync(0xffffffffu, v, o);
            v = MAX ? fmaxf(v, u) : v + u;
        }
        if (lane == 0) sh[0] = v;
    }
    __syncthreads();
    float r = sh[0];
    __syncthreads();
    return r;
}

// ---------------- LayerNorm (rounds output to tf32: feeds GEMM A) ----------------
__global__ void ln_kernel(const float* __restrict__ x, const float* __restrict__ g,
                          const float* __restrict__ beta, float* __restrict__ out) {
    size_t base = (size_t)blockIdx.x * HID_;
    const float4* xp = reinterpret_cast<const float4*>(x + base);
    int t = threadIdx.x;
    float4 v = xp[t];
    float s = v.x + v.y + v.z + v.w;
    s = block_reduce_256<false>(s);
    float mean = s * (1.0f / HID_);
    float dx = v.x - mean, dy = v.y - mean, dz = v.z - mean, dw = v.w - mean;
    float q = dx*dx + dy*dy + dz*dz + dw*dw;
    q = block_reduce_256<false>(q);
    float r = rsqrtf(q * (1.0f / HID_) + 1e-5f);
    float4 gv = reinterpret_cast<const float4*>(g)[t];
    float4 bv = reinterpret_cast<const float4*>(beta)[t];
    float4 o;
    o.x = tf32r(dx * r * gv.x + bv.x);
    o.y = tf32r(dy * r * gv.y + bv.y);
    o.z = tf32r(dz * r * gv.z + bv.z);
    o.w = tf32r(dw * r * gv.w + bv.w);
    reinterpret_cast<float4*>(out + base)[t] = o;
}

// ---------------- softmax (rounds output: feeds ctx GEMM A) ----------------
__global__ void softmax_kernel(float* __restrict__ s) {
    size_t base = (size_t)blockIdx.x * SS_;
    float4* p = reinterpret_cast<float4*>(s + base);
    int t = threadIdx.x;
    float4 a = p[t], b = p[t + 256];
    float m = fmaxf(fmaxf(fmaxf(a.x, a.y), fmaxf(a.z, a.w)),
                    fmaxf(fmaxf(b.x, b.y), fmaxf(b.z, b.w)));
    m = block_reduce_256<true>(m);
    a.x = expf(a.x - m); a.y = expf(a.y - m); a.z = expf(a.z - m); a.w = expf(a.w - m);
    b.x = expf(b.x - m); b.y = expf(b.y - m); b.z = expf(b.z - m); b.w = expf(b.w - m);
    float sum = a.x + a.y + a.z + a.w + b.x + b.y + b.z + b.w;
    sum = block_reduce_256<false>(sum);
    float inv = 1.0f / sum;
    a.x = tf32r(a.x * inv); a.y = tf32r(a.y * inv);
    a.z = tf32r(a.z * inv); a.w = tf32r(a.w * inv);
    b.x = tf32r(b.x * inv); b.y = tf32r(b.y * inv);
    b.z = tf32r(b.z * inv); b.w = tf32r(b.w * inv);
    p[t] = a; p[t + 256] = b;
}

// ---------------- transpose V (rounds output: feeds ctx GEMM B) ----------------
__global__ void transpose_v_kernel(const float* __restrict__ v, float* __restrict__ vt) {
    __shared__ float t[32][33];
    int bz = blockIdx.y;
    int b = bz / (NH_ * 2);
    int rem = bz % (NH_ * 2);
    int h = rem >> 1;
    int d0 = (rem & 1) * 32;
    int s0 = blockIdx.x * 32;
    int tx = threadIdx.x & 31, ty = threadIdx.x >> 5;
    #pragma unroll
    for (int i = 0; i < 32; i += 8)
        t[ty + i][tx] = v[((size_t)b * SS_ + s0 + ty + i) * HID_ + h * 64 + d0 + tx];
    __syncthreads();
    #pragma unroll
    for (int i = 0; i < 32; i += 8)
        vt[(((size_t)b * NH_ + h) * 64 + d0 + ty + i) * SS_ + s0 + tx] = tf32r(t[tx][ty + i]);
}

// ---------------- tf32 mma.sync GEMM ----------------
// C[M,N] = A[M,K] @ B[N,K]^T (+ epilogue). Operands must be pre-rounded to tf32.
// BM=128, BN in {128,64}, BK=32. 256 threads, warps 2(M) x 4(N); warp tile 64 x BN/4.
// EPI: 0=+bias  1=*scale+(mask-1)*1e4  2=gelu(+bias)  3=+bias+residual
// RND: round C to tf32 (when C feeds another GEMM).
template<int BN, int EPI, bool RND>
__global__ __launch_bounds__(256, 2) void tc_gemm(
    int M, int N, int K,
    const float* __restrict__ A,  int lda, long long sAb, long long sAh,
    const float* __restrict__ Bm, int ldb, long long sBb, long long sBh,
    float* __restrict__ C,        int ldc, long long sCb, long long sCh,
    const float* __restrict__ bias, const float* __restrict__ residual,
    const float* __restrict__ mask, float scale)
{
    constexpr int RS  = 36;          // smem row stride (floats), conflict-free
    constexpr int ASZ = 128 * RS;    // floats per A stage
    constexpr int BSZ = BN * RS;
    constexpr int WN  = BN / 4;      // warp n extent
    constexpr int NT  = WN / 8;      // n-tiles per warp

    extern __shared__ __align__(16) float smem[];

    const int tid  = threadIdx.x;
    const int wid  = tid >> 5, lane = tid & 31;
    const int wm   = wid >> 2, wn = wid & 3;
    const int bz   = blockIdx.z, bb = bz >> 4, hh = bz & 15;
    A  += bb * sAb + hh * sAh;
    Bm += bb * sBb + hh * sBh;
    C  += bb * sCb + hh * sCh;
    const int row0 = blockIdx.y * 128;
    const int col0 = blockIdx.x * BN;

    const uint32_t sbase = smem_u32(smem);

    float acc[4][NT][4];
    #pragma unroll
    for (int i = 0; i < 4; i++)
        #pragma unroll
        for (int j = 0; j < NT; j++)
            #pragma unroll
            for (int e = 0; e < 4; e++) acc[i][j][e] = 0.0f;

    const int nk = K >> 5;

    auto load_stage = [&](int i, int s) {
        const int k0 = i << 5;
        uint32_t abase = sbase + (uint32_t)(s * (ASZ + BSZ)) * 4u;
        uint32_t bbase = abase + (uint32_t)ASZ * 4u;
        #pragma unroll
        for (int u = 0; u < 4; u++) {
            int idx = tid + u * 256;
            int r = idx >> 3, c4 = (idx & 7) << 2;
            CP16(abase + (uint32_t)(r * RS + c4) * 4u,
                 A + (size_t)(row0 + r) * lda + k0 + c4);
        }
        #pragma unroll
        for (int u = 0; u < BN / 32; u++) {
            int idx = tid + u * 256;
            int r = idx >> 3, c4 = (idx & 7) << 2;
            CP16(bbase + (uint32_t)(r * RS + c4) * 4u,
                 Bm + (size_t)(col0 + r) * ldb + k0 + c4);
        }
        CP_COMMIT();
    };

    load_stage(0, 0);

    for (int i = 0; i < nk; i++) {
        const int s = i & 1;
        if (i + 1 < nk) { load_stage(i + 1, s ^ 1); CP_WAIT1(); }
        else            { CP_WAIT0(); }
        __syncthreads();

        const float* As = smem + s * (ASZ + BSZ);
        const float* Bs = As + ASZ;

        #pragma unroll
        for (int kk = 0; kk < 4; kk++) {
            uint32_t af[4][4];
            #pragma unroll
            for (int mt = 0; mt < 4; mt++) {
                int r  = wm * 64 + mt * 16 + (lane >> 2);
                int kb = kk * 8 + (lane & 3);
                af[mt][0] = __float_as_uint(As[r * RS + kb]);
                af[mt][1] = __float_as_uint(As[(r + 8) * RS + kb]);
                af[mt][2] = __float_as_uint(As[r * RS + kb + 4]);
                af[mt][3] = __float_as_uint(As[(r + 8) * RS + kb + 4]);
            }
            #pragma unroll
            for (int nt = 0; nt < NT; nt++) {
                int cix = wn * WN + nt * 8 + (lane >> 2);
                uint32_t b0 = __float_as_uint(Bs[cix * RS + kk * 8 + (lane & 3)]);
                uint32_t b1 = __float_as_uint(Bs[cix * RS + kk * 8 + 4 + (lane & 3)]);
                #pragma unroll
                for (int mt = 0; mt < 4; mt++)
                    mma1688(acc[mt][nt], af[mt], b0, b1);
            }
        }
        __syncthreads();
    }

    // ---------------- epilogue ----------------
    #pragma unroll
    for (int mt = 0; mt < 4; mt++) {
        #pragma unroll
        for (int nt = 0; nt < NT; nt++) {
            int r0 = row0 + wm * 64 + mt * 16 + (lane >> 2);
            int c0 = col0 + wn * WN + nt * 8 + 2 * (lane & 3);
            #pragma unroll
            for (int half = 0; half < 2; half++) {      // rows r0, r0+8
                int r = r0 + half * 8;
                float v0 = acc[mt][nt][2 * half + 0];
                float v1 = acc[mt][nt][2 * half + 1];
                if (EPI == 1) {
                    float m0 = __ldg(&mask[(size_t)bb * N + c0]);
                    float m1 = __ldg(&mask[(size_t)bb * N + c0 + 1]);
                    v0 = v0 * scale + (m0 - 1.0f) * 10000.0f;
                    v1 = v1 * scale + (m1 - 1.0f) * 10000.0f;
                } else {
                    if (bias) {
                        v0 += __ldg(&bias[c0]);
                        v1 += __ldg(&bias[c0 + 1]);
                    }
                }
                if (EPI == 2) {
                    v0 = 0.5f * v0 * (1.0f + erff(v0 * 0.70710678118654752f));
                    v1 = 0.5f * v1 * (1.0f + erff(v1 * 0.70710678118654752f));
                }
                if (EPI == 3) {
                    float2 rr = *reinterpret_cast<const float2*>(
                        residual + (size_t)r * ldc + c0);
                    v0 += rr.x; v1 += rr.y;
                }
                if (RND) { v0 = tf32r(v0); v1 = tf32r(v1); }
                float2 o; o.x = v0; o.y = v1;
                *reinterpret_cast<float2*>(C + (size_t)r * ldc + c0) = o;
            }
        }
    }
}

// ---------------- launch ----------------
extern "C" void kernel_launch(void* const* d_in, const int* in_sizes, int n_in,
                              void* d_out, int out_size) {
    const float* x   = (const float*)d_in[0];
    const float* am  = (const float*)d_in[1];
    const float* Wq  = (const float*)d_in[2];
    const float* bq  = (const float*)d_in[3];
    const float* Wk  = (const float*)d_in[4];
    const float* bk  = (const float*)d_in[5];
    const float* Wv  = (const float*)d_in[6];
    const float* bv  = (const float*)d_in[7];
    const float* Wo  = (const float*)d_in[8];
    const float* bo  = (const float*)d_in[9];
    const float* W1  = (const float*)d_in[10];
    const float* b1  = (const float*)d_in[11];
    const float* W2  = (const float*)d_in[12];
    const float* b2  = (const float*)d_in[13];
    const float* g1  = (const float*)d_in[14];
    const float* be1 = (const float*)d_in[15];
    const float* g2  = (const float*)d_in[16];
    const float* be2 = (const float*)d_in[17];
    float* out = (float*)d_out;

    float *h, *q, *k, *v, *vt, *sc, *ctx, *x2, *h2, *ff, *wr;
    cudaGetSymbolAddress((void**)&h,   g_h);
    cudaGetSymbolAddress((void**)&q,   g_q);
    cudaGetSymbolAddress((void**)&k,   g_k);
    cudaGetSymbolAddress((void**)&v,   g_v);
    cudaGetSymbolAddress((void**)&vt,  g_vt);
    cudaGetSymbolAddress((void**)&sc,  g_sc);
    cudaGetSymbolAddress((void**)&ctx, g_ctx);
    cudaGetSymbolAddress((void**)&x2,  g_x2);
    cudaGetSymbolAddress((void**)&h2,  g_h2);
    cudaGetSymbolAddress((void**)&ff,  g_ff);
    cudaGetSymbolAddress((void**)&wr,  g_wr);

    float* rWq = wr;
    float* rWk = wr + 1 * 1024 * 1024;
    float* rWv = wr + 2 * 1024 * 1024;
    float* rWo = wr + 3 * 1024 * 1024;
    float* rW1 = wr + 4 * 1024 * 1024;
    float* rW2 = wr + 8 * 1024 * 1024;

    const int SM128 = 2 * (128 * 36 + 128 * 36) * 4;  // 73728
    const int SM64  = 2 * (128 * 36 + 64  * 36) * 4;  // 55296
    cudaFuncSetAttribute(tc_gemm<128,0,true >, cudaFuncAttributeMaxDynamicSharedMemorySize, SM128);
    cudaFuncSetAttribute(tc_gemm<128,0,false>, cudaFuncAttributeMaxDynamicSharedMemorySize, SM128);
    cudaFuncSetAttribute(tc_gemm<128,1,false>, cudaFuncAttributeMaxDynamicSharedMemorySize, SM128);
    cudaFuncSetAttribute(tc_gemm<128,2,true >, cudaFuncAttributeMaxDynamicSharedMemorySize, SM128);
    cudaFuncSetAttribute(tc_gemm<128,3,false>, cudaFuncAttributeMaxDynamicSharedMemorySize, SM128);
    cudaFuncSetAttribute(tc_gemm<64,0,true  >, cudaFuncAttributeMaxDynamicSharedMemorySize, SM64);

    const long long sQb = (long long)SS_ * HID_;
    const long long sQh = HD_;
    const long long sSb = (long long)NH_ * SS_ * SS_;
    const long long sSh = (long long)SS_ * SS_;
    const long long sVb = (long long)NH_ * HD_ * SS_;
    const long long sVh = (long long)HD_ * SS_;

    dim3 blk(256);

    // one-time (per launch) weight rounding to tf32
    round_kernel<<<(1024*1024/4 + 255)/256, blk>>>(Wq, rWq, 1024*1024/4);
    round_kernel<<<(1024*1024/4 + 255)/256, blk>>>(Wk, rWk, 1024*1024/4);
    round_kernel<<<(1024*1024/4 + 255)/256, blk>>>(Wv, rWv, 1024*1024/4);
    round_kernel<<<(1024*1024/4 + 255)/256, blk>>>(Wo, rWo, 1024*1024/4);
    round_kernel<<<(4*1024*1024/4 + 255)/256, blk>>>(W1, rW1, 4*1024*1024/4);
    round_kernel<<<(4*1024*1024/4 + 255)/256, blk>>>(W2, rW2, 4*1024*1024/4);

    // h = LN1(x)  (tf32-rounded)
    ln_kernel<<<TOK_, blk>>>(x, g1, be1, h);

    // q/k/v = h @ W^T + b   (q,k rounded; v rounded later in transpose)
    tc_gemm<128,0,true ><<<dim3(HID_/128, TOK_/128, 1), blk, SM128>>>(TOK_, HID_, HID_,
        h, HID_, 0, 0,  rWq, HID_, 0, 0,  q, HID_, 0, 0,  bq, nullptr, nullptr, 0.f);
    tc_gemm<128,0,true ><<<dim3(HID_/128, TOK_/128, 1), blk, SM128>>>(TOK_, HID_, HID_,
        h, HID_, 0, 0,  rWk, HID_, 0, 0,  k, HID_, 0, 0,  bk, nullptr, nullptr, 0.f);
    tc_gemm<128,0,false><<<dim3(HID_/128, TOK_/128, 1), blk, SM128>>>(TOK_, HID_, HID_,
        h, HID_, 0, 0,  rWv, HID_, 0, 0,  v, HID_, 0, 0,  bv, nullptr, nullptr, 0.f);

    // scores = q @ k^T * 0.125 + (mask-1)*1e4
    tc_gemm<128,1,false><<<dim3(SS_/128, SS_/128, BB_*NH_), blk, SM128>>>(SS_, SS_, HD_,
        q, HID_, sQb, sQh,  k, HID_, sQb, sQh,  sc, SS_, sSb, sSh,
        nullptr, nullptr, am, 0.125f);

    softmax_kernel<<<BB_*NH_*SS_, blk>>>(sc);

    transpose_v_kernel<<<dim3(SS_/32, BB_*NH_*2), blk>>>(v, vt);

    // ctx = attn @ v   (rounded: feeds Wo GEMM)
    tc_gemm<64,0,true ><<<dim3(1, SS_/128, BB_*NH_), blk, SM64>>>(SS_, HD_, SS_,
        sc, SS_, sSb, sSh,  vt, SS_, sVb, sVh,  ctx, HID_, sQb, sQh,
        nullptr, nullptr, nullptr, 0.f);

    // x2 = x + ctx @ Wo^T + bo   (full fp32)
    tc_gemm<128,3,false><<<dim3(HID_/128, TOK_/128, 1), blk, SM128>>>(TOK_, HID_, HID_,
        ctx, HID_, 0, 0,  rWo, HID_, 0, 0,  x2, HID_, 0, 0,  bo, x, nullptr, 0.f);

    // h2 = LN2(x2)  (rounded)
    ln_kernel<<<TOK_, blk>>>(x2, g2, be2, h2);

    // ff = gelu(h2 @ W1^T + b1)  (rounded: feeds W2 GEMM)
    tc_gemm<128,2,true ><<<dim3(FF_/128, TOK_/128, 1), blk, SM128>>>(TOK_, FF_, HID_,
        h2, HID_, 0, 0,  rW1, HID_, 0, 0,  ff, FF_, 0, 0,  b1, nullptr, nullptr, 0.f);

    // out = x2 + ff @ W2^T + b2  (full fp32)
    tc_gemm<128,3,false><<<dim3(HID_/128, TOK_/128, 1), blk, SM128>>>(TOK_, HID_, FF_,
        ff, FF_, 0, 0,  rW2, FF_, 0, 0,  out, HID_, 0, 0,  b2, x2, nullptr, 0.f);
}

// round 5
// speedup vs baseline: 3.5446x; 1.0933x over previous
#include <cuda_runtime.h>
#include <math.h>
#include <stdint.h>

#define BB_   2
#define SS_   2048
#define HID_  1024
#define NH_   16
#define HD_   64
#define FF_   4096
#define TOK_  (BB_*SS_)   // 4096

// ---------------- scratch ----------------
__device__ float g_h  [TOK_*HID_];
__device__ float g_q  [TOK_*HID_];
__device__ float g_k  [TOK_*HID_];
__device__ float g_v  [TOK_*HID_];
__device__ float g_vt [TOK_*HID_];                 // [B*H, 64, S]
__device__ float g_ctx[TOK_*HID_];
__device__ float g_x2 [TOK_*HID_];
__device__ float g_h2 [TOK_*HID_];
__device__ float g_ff [TOK_*FF_];
__device__ float g_wr [12*1024*1024];              // tf32-rounded weights

// ---------------- helpers ----------------
__device__ __forceinline__ float tf32r(float x) {
    float y;
    asm("cvt.rna.tf32.f32 %0, %1;" : "=f"(y) : "f"(x));
    return y;
}
__device__ __forceinline__ uint32_t smem_u32(const void* p) {
    uint32_t a;
    asm("{ .reg .u64 t; cvta.to.shared.u64 t, %1; cvt.u32.u64 %0, t; }" : "=r"(a) : "l"(p));
    return a;
}
#define CP16(dst, src) \
    asm volatile("cp.async.cg.shared.global [%0], [%1], 16;" :: "r"(dst), "l"(src) : "memory")
#define CP_COMMIT() asm volatile("cp.async.commit_group;" ::: "memory")
#define CP_WAIT1()  asm volatile("cp.async.wait_group 1;" ::: "memory")
#define CP_WAIT0()  asm volatile("cp.async.wait_group 0;" ::: "memory")

__device__ __forceinline__ void mma1688(float* c, const uint32_t* a, uint32_t b0, uint32_t b1) {
    asm volatile(
        "mma.sync.aligned.m16n8k8.row.col.f32.tf32.tf32.f32 "
        "{%0,%1,%2,%3}, {%4,%5,%6,%7}, {%8,%9}, {%0,%1,%2,%3};"
        : "+f"(c[0]), "+f"(c[1]), "+f"(c[2]), "+f"(c[3])
        : "r"(a[0]), "r"(a[1]), "r"(a[2]), "r"(a[3]), "r"(b0), "r"(b1));
}

// ---------------- elementwise tf32 round ----------------
__global__ void round_kernel(const float* __restrict__ src, float* __restrict__ dst, int n4) {
    int i = blockIdx.x * blockDim.x + threadIdx.x;
    if (i < n4) {
        float4 v = reinterpret_cast<const float4*>(src)[i];
        v.x = tf32r(v.x); v.y = tf32r(v.y); v.z = tf32r(v.z); v.w = tf32r(v.w);
        reinterpret_cast<float4*>(dst)[i] = v;
    }
}

// ---------------- block reduction ----------------
template<bool MAX>
__device__ __forceinline__ float block_reduce_256(float v) {
    __shared__ float sh[8];
    int lane = threadIdx.x & 31, w = threadIdx.x >> 5;
    #pragma unroll
    for (int o = 16; o; o >>= 1) {
        float u = __shfl_xor_sync(0xffffffffu, v, o);
        v = MAX ? fmaxf(v, u) : v + u;
    }
    if (lane == 0) sh[w] = v;
    __syncthreads();
    if (w == 0) {
        v = sh[lane & 7];
        #pragma unroll
        for (int o = 4; o; o >>= 1) {
            float u = __shfl_xor_sync(0xffffffffu, v, o);
            v = MAX ? fmaxf(v, u) : v + u;
        }
        if (lane == 0) sh[0] = v;
    }
    __syncthreads();
    float r = sh[0];
    __syncthreads();
    return r;
}

// ---------------- LayerNorm (rounds output to tf32: feeds GEMM A) ----------------
__global__ void ln_kernel(const float* __restrict__ x, const float* __restrict__ g,
                          const float* __restrict__ beta, float* __restrict__ out) {
    size_t base = (size_t)blockIdx.x * HID_;
    const float4* xp = reinterpret_cast<const float4*>(x + base);
    int t = threadIdx.x;
    float4 v = xp[t];
    float s = v.x + v.y + v.z + v.w;
    s = block_reduce_256<false>(s);
    float mean = s * (1.0f / HID_);
    float dx = v.x - mean, dy = v.y - mean, dz = v.z - mean, dw = v.w - mean;
    float q = dx*dx + dy*dy + dz*dz + dw*dw;
    q = block_reduce_256<false>(q);
    float r = rsqrtf(q * (1.0f / HID_) + 1e-5f);
    float4 gv = reinterpret_cast<const float4*>(g)[t];
    float4 bv = reinterpret_cast<const float4*>(beta)[t];
    float4 o;
    o.x = tf32r(dx * r * gv.x + bv.x);
    o.y = tf32r(dy * r * gv.y + bv.y);
    o.z = tf32r(dz * r * gv.z + bv.z);
    o.w = tf32r(dw * r * gv.w + bv.w);
    reinterpret_cast<float4*>(out + base)[t] = o;
}

// ---------------- transpose V (rounds output: feeds flash P@V) ----------------
__global__ void transpose_v_kernel(const float* __restrict__ v, float* __restrict__ vt) {
    __shared__ float t[32][33];
    int bz = blockIdx.y;
    int b = bz / (NH_ * 2);
    int rem = bz % (NH_ * 2);
    int h = rem >> 1;
    int d0 = (rem & 1) * 32;
    int s0 = blockIdx.x * 32;
    int tx = threadIdx.x & 31, ty = threadIdx.x >> 5;
    #pragma unroll
    for (int i = 0; i < 32; i += 8)
        t[ty + i][tx] = v[((size_t)b * SS_ + s0 + ty + i) * HID_ + h * 64 + d0 + tx];
    __syncthreads();
    #pragma unroll
    for (int i = 0; i < 32; i += 8)
        vt[(((size_t)b * NH_ + h) * 64 + d0 + ty + i) * SS_ + s0 + tx] = tf32r(t[tx][ty + i]);
}

// ---------------- fused flash attention ----------------
// CTA = 128 q-rows of one (batch, head). KV tiles of 64 keys, cp.async double-buffered.
// Warps 2(M) x 4(N); warp tile 64x16 in BOTH phases. P via smem round-trip.
// 64-float-wide tiles: stage loops use r = idx>>4, c4 = (idx&15)<<2.
#define FRS 68
#define OFF_Q  0
#define OFF_K  (128*FRS)
#define OFF_V  (OFF_K + 2*64*FRS)
#define OFF_P  (OFF_V + 2*64*FRS)
#define OFF_MD (OFF_P + 128*FRS)
#define OFF_MX (OFF_MD + 2048)
#define OFF_SU (OFF_MX + 512)
#define FL_SMEM ((OFF_SU + 512) * 4)

__global__ __launch_bounds__(256, 1) void flash_kernel(
    const float* __restrict__ q, const float* __restrict__ k,
    const float* __restrict__ vt, const float* __restrict__ am,
    float* __restrict__ ctx)
{
    extern __shared__ float sm[];
    float* Qs   = sm + OFF_Q;
    float* Ks   = sm + OFF_K;
    float* Vs   = sm + OFF_V;
    float* Ps   = sm + OFF_P;
    float* Madd = sm + OFF_MD;
    float* Pmax = sm + OFF_MX;
    float* Psum = sm + OFF_SU;

    const int tid = threadIdx.x, lane = tid & 31, wid = tid >> 5;
    const int wm = wid >> 2, wn = wid & 3;
    const int qt = blockIdx.x, bh = blockIdx.y;
    const int bb = bh >> 4, hh = bh & 15;
    const int q0 = qt * 128;

    const float* Qg = q  + ((size_t)bb * SS_ + q0) * HID_ + hh * 64;
    const float* Kg = k  + (size_t)bb * SS_ * HID_ + hh * 64;
    const float* Vg = vt + (size_t)bh * 64 * SS_;

    const uint32_t sb = smem_u32(sm);

    // Q tile (128 rows x 64 cols) -> smem: 2048 float4 ops, 8 per thread
    #pragma unroll
    for (int u = 0; u < 8; u++) {
        int idx = tid + u * 256;
        int r = idx >> 4, c4 = (idx & 15) << 2;
        CP16(sb + (uint32_t)((OFF_Q + r * FRS + c4) * 4), Qg + (size_t)r * HID_ + c4);
    }
    CP_COMMIT();
    // mask-add row for this batch
    #pragma unroll
    for (int u = 0; u < 8; u++) {
        int i = tid + u * 256;
        Madd[i] = (__ldg(&am[(size_t)bb * SS_ + i]) - 1.0f) * 10000.0f;
    }

    auto load_kv = [&](int j, int s) {
        const int j0 = j * 64;
        uint32_t kb = sb + (uint32_t)((OFF_K + s * 64 * FRS) * 4);
        uint32_t vb = sb + (uint32_t)((OFF_V + s * 64 * FRS) * 4);
        // K tile: 64 key-rows x 64 dh cols = 1024 float4 ops
        #pragma unroll
        for (int u = 0; u < 4; u++) {
            int idx = tid + u * 256;
            int r = idx >> 4, c4 = (idx & 15) << 2;
            CP16(kb + (uint32_t)((r * FRS + c4) * 4), Kg + (size_t)(j0 + r) * HID_ + c4);
        }
        // V tile: 64 dh-rows x 64 key cols
        #pragma unroll
        for (int u = 0; u < 4; u++) {
            int idx = tid + u * 256;
            int r = idx >> 4, c4 = (idx & 15) << 2;
            CP16(vb + (uint32_t)((r * FRS + c4) * 4), Vg + (size_t)r * SS_ + j0 + c4);
        }
        CP_COMMIT();
    };
    load_kv(0, 0);

    float ctxa[4][2][4] = {};
    float mrow[4][2], lrow[4][2];
    #pragma unroll
    for (int mt = 0; mt < 4; mt++) {
        mrow[mt][0] = -1e30f; mrow[mt][1] = -1e30f;
        lrow[mt][0] = 0.f;    lrow[mt][1] = 0.f;
    }

    const int IT = SS_ / 64;   // 32
    for (int j = 0; j < IT; j++) {
        const int s = j & 1;
        __syncthreads();                       // stage s^1 reads (iter j-1) done
        if (j + 1 < IT) { load_kv(j + 1, s ^ 1); CP_WAIT1(); }
        else            { CP_WAIT0(); }
        __syncthreads();                       // stage s ready

        // ---- S = Q @ K^T (128x64, K=64) ----
        float sacc[4][2][4] = {};
        const float* KsS = Ks + s * 64 * FRS;
        #pragma unroll
        for (int kk = 0; kk < 8; kk++) {
            uint32_t af[4][4];
            #pragma unroll
            for (int mt = 0; mt < 4; mt++) {
                int r = wm * 64 + mt * 16 + (lane >> 2);
                int kb2 = kk * 8 + (lane & 3);
                af[mt][0] = __float_as_uint(Qs[r * FRS + kb2]);
                af[mt][1] = __float_as_uint(Qs[(r + 8) * FRS + kb2]);
                af[mt][2] = __float_as_uint(Qs[r * FRS + kb2 + 4]);
                af[mt][3] = __float_as_uint(Qs[(r + 8) * FRS + kb2 + 4]);
            }
            #pragma unroll
            for (int nt = 0; nt < 2; nt++) {
                int cix = wn * 16 + nt * 8 + (lane >> 2);
                uint32_t b0 = __float_as_uint(KsS[cix * FRS + kk * 8 + (lane & 3)]);
                uint32_t b1 = __float_as_uint(KsS[cix * FRS + kk * 8 + 4 + (lane & 3)]);
                #pragma unroll
                for (int mt = 0; mt < 4; mt++) mma1688(sacc[mt][nt], af[mt], b0, b1);
            }
        }

        // ---- scale + mask, local row max ----
        const int j0 = j * 64;
        float lmax[4][2];
        #pragma unroll
        for (int mt = 0; mt < 4; mt++) { lmax[mt][0] = -1e30f; lmax[mt][1] = -1e30f; }
        #pragma unroll
        for (int nt = 0; nt < 2; nt++) {
            int cl = wn * 16 + nt * 8 + 2 * (lane & 3);
            float2 md = *reinterpret_cast<const float2*>(&Madd[j0 + cl]);
            #pragma unroll
            for (int mt = 0; mt < 4; mt++) {
                sacc[mt][nt][0] = sacc[mt][nt][0] * 0.125f + md.x;
                sacc[mt][nt][1] = sacc[mt][nt][1] * 0.125f + md.y;
                sacc[mt][nt][2] = sacc[mt][nt][2] * 0.125f + md.x;
                sacc[mt][nt][3] = sacc[mt][nt][3] * 0.125f + md.y;
                lmax[mt][0] = fmaxf(lmax[mt][0], fmaxf(sacc[mt][nt][0], sacc[mt][nt][1]));
                lmax[mt][1] = fmaxf(lmax[mt][1], fmaxf(sacc[mt][nt][2], sacc[mt][nt][3]));
            }
        }
        #pragma unroll
        for (int mt = 0; mt < 4; mt++)
            #pragma unroll
            for (int h2 = 0; h2 < 2; h2++) {
                float v = lmax[mt][h2];
                v = fmaxf(v, __shfl_xor_sync(0xffffffffu, v, 1));
                v = fmaxf(v, __shfl_xor_sync(0xffffffffu, v, 2));
                lmax[mt][h2] = v;
            }
        if ((lane & 3) == 0) {
            #pragma unroll
            for (int mt = 0; mt < 4; mt++)
                #pragma unroll
                for (int h2 = 0; h2 < 2; h2++) {
                    int row = wm * 64 + mt * 16 + h2 * 8 + (lane >> 2);
                    Pmax[wn * 128 + row] = lmax[mt][h2];
                }
        }
        __syncthreads();

        // ---- m update, alpha, P = exp, local sums ----
        float alpha[4][2], lsum[4][2];
        #pragma unroll
        for (int mt = 0; mt < 4; mt++)
            #pragma unroll
            for (int h2 = 0; h2 < 2; h2++) {
                int row = wm * 64 + mt * 16 + h2 * 8 + (lane >> 2);
                float tm = fmaxf(fmaxf(Pmax[row], Pmax[128 + row]),
                                 fmaxf(Pmax[256 + row], Pmax[384 + row]));
                float mo = mrow[mt][h2];
                float mn = fmaxf(mo, tm);
                mrow[mt][h2]  = mn;
                alpha[mt][h2] = __expf(mo - mn);
                lsum[mt][h2]  = 0.f;
            }
        #pragma unroll
        for (int nt = 0; nt < 2; nt++) {
            int cl = wn * 16 + nt * 8 + 2 * (lane & 3);
            #pragma unroll
            for (int mt = 0; mt < 4; mt++)
                #pragma unroll
                for (int h2 = 0; h2 < 2; h2++) {
                    float p0 = __expf(sacc[mt][nt][2 * h2 + 0] - mrow[mt][h2]);
                    float p1 = __expf(sacc[mt][nt][2 * h2 + 1] - mrow[mt][h2]);
                    lsum[mt][h2] += p0 + p1;
                    int row = wm * 64 + mt * 16 + h2 * 8 + (lane >> 2);
                    float2 pp; pp.x = tf32r(p0); pp.y = tf32r(p1);
                    *reinterpret_cast<float2*>(&Ps[row * FRS + cl]) = pp;
                }
        }
        #pragma unroll
        for (int mt = 0; mt < 4; mt++)
            #pragma unroll
            for (int h2 = 0; h2 < 2; h2++) {
                float v = lsum[mt][h2];
                v += __shfl_xor_sync(0xffffffffu, v, 1);
                v += __shfl_xor_sync(0xffffffffu, v, 2);
                lsum[mt][h2] = v;
            }
        if ((lane & 3) == 0) {
            #pragma unroll
            for (int mt = 0; mt < 4; mt++)
                #pragma unroll
                for (int h2 = 0; h2 < 2; h2++) {
                    int row = wm * 64 + mt * 16 + h2 * 8 + (lane >> 2);
                    Psum[wn * 128 + row] = lsum[mt][h2];
                }
        }
        __syncthreads();                       // Ps + Psum visible
        #pragma unroll
        for (int mt = 0; mt < 4; mt++)
            #pragma unroll
            for (int h2 = 0; h2 < 2; h2++) {
                int row = wm * 64 + mt * 16 + h2 * 8 + (lane >> 2);
                float ts = Psum[row] + Psum[128 + row] + Psum[256 + row] + Psum[384 + row];
                lrow[mt][h2] = lrow[mt][h2] * alpha[mt][h2] + ts;
                #pragma unroll
                for (int nt = 0; nt < 2; nt++) {
                    ctxa[mt][nt][2 * h2 + 0] *= alpha[mt][h2];
                    ctxa[mt][nt][2 * h2 + 1] *= alpha[mt][h2];
                }
            }

        // ---- ctx += P @ V^T (128x64, K=64 keys) ----
        const float* VsS = Vs + s * 64 * FRS;
        #pragma unroll
        for (int kk = 0; kk < 8; kk++) {
            uint32_t af[4][4];
            #pragma unroll
            for (int mt = 0; mt < 4; mt++) {
                int r = wm * 64 + mt * 16 + (lane >> 2);
                int kb2 = kk * 8 + (lane & 3);
                af[mt][0] = __float_as_uint(Ps[r * FRS + kb2]);
                af[mt][1] = __float_as_uint(Ps[(r + 8) * FRS + kb2]);
                af[mt][2] = __float_as_uint(Ps[r * FRS + kb2 + 4]);
                af[mt][3] = __float_as_uint(Ps[(r + 8) * FRS + kb2 + 4]);
            }
            #pragma unroll
            for (int nt = 0; nt < 2; nt++) {
                int cix = wn * 16 + nt * 8 + (lane >> 2);
                uint32_t b0 = __float_as_uint(VsS[cix * FRS + kk * 8 + (lane & 3)]);
                uint32_t b1 = __float_as_uint(VsS[cix * FRS + kk * 8 + 4 + (lane & 3)]);
                #pragma unroll
                for (int mt = 0; mt < 4; mt++) mma1688(ctxa[mt][nt], af[mt], b0, b1);
            }
        }
    }

    // ---- finalize: ctx / l, round, store ----
    #pragma unroll
    for (int mt = 0; mt < 4; mt++)
        #pragma unroll
        for (int h2 = 0; h2 < 2; h2++) {
            int row = wm * 64 + mt * 16 + h2 * 8 + (lane >> 2);
            float inv = 1.0f / lrow[mt][h2];
            #pragma unroll
            for (int nt = 0; nt < 2; nt++) {
                int cl = wn * 16 + nt * 8 + 2 * (lane & 3);
                float2 o;
                o.x = tf32r(ctxa[mt][nt][2 * h2 + 0] * inv);
                o.y = tf32r(ctxa[mt][nt][2 * h2 + 1] * inv);
                *reinterpret_cast<float2*>(
                    ctx + ((size_t)bb * SS_ + q0 + row) * HID_ + hh * 64 + cl) = o;
            }
        }
}

// ---------------- tf32 mma.sync GEMM ----------------
template<int BN, int EPI, bool RND>
__global__ __launch_bounds__(256, 2) void tc_gemm(
    int M, int N, int K,
    const float* __restrict__ A,  int lda, long long sAb, long long sAh,
    const float* __restrict__ Bm, int ldb, long long sBb, long long sBh,
    float* __restrict__ C,        int ldc, long long sCb, long long sCh,
    const float* __restrict__ bias, const float* __restrict__ residual,
    const float* __restrict__ mask, float scale)
{
    constexpr int RS  = 36;
    constexpr int ASZ = 128 * RS;
    constexpr int BSZ = BN * RS;
    constexpr int WN  = BN / 4;
    constexpr int NT  = WN / 8;

    extern __shared__ __align__(16) float smem[];

    const int tid  = threadIdx.x;
    const int wid  = tid >> 5, lane = tid & 31;
    const int wm   = wid >> 2, wn = wid & 3;
    const int bz   = blockIdx.z, bb = bz >> 4, hh = bz & 15;
    A  += bb * sAb + hh * sAh;
    Bm += bb * sBb + hh * sBh;
    C  += bb * sCb + hh * sCh;
    const int row0 = blockIdx.y * 128;
    const int col0 = blockIdx.x * BN;

    const uint32_t sbase = smem_u32(smem);

    float acc[4][NT][4];
    #pragma unroll
    for (int i = 0; i < 4; i++)
        #pragma unroll
        for (int j = 0; j < NT; j++)
            #pragma unroll
            for (int e = 0; e < 4; e++) acc[i][j][e] = 0.0f;

    const int nk = K >> 5;

    auto load_stage = [&](int i, int s) {
        const int k0 = i << 5;
        uint32_t abase = sbase + (uint32_t)(s * (ASZ + BSZ)) * 4u;
        uint32_t bbase = abase + (uint32_t)ASZ * 4u;
        #pragma unroll
        for (int u = 0; u < 4; u++) {
            int idx = tid + u * 256;
            int r = idx >> 3, c4 = (idx & 7) << 2;
            CP16(abase + (uint32_t)(r * RS + c4) * 4u,
                 A + (size_t)(row0 + r) * lda + k0 + c4);
        }
        #pragma unroll
        for (int u = 0; u < BN / 32; u++) {
            int idx = tid + u * 256;
            int r = idx >> 3, c4 = (idx & 7) << 2;
            CP16(bbase + (uint32_t)(r * RS + c4) * 4u,
                 Bm + (size_t)(col0 + r) * ldb + k0 + c4);
        }
        CP_COMMIT();
    };

    load_stage(0, 0);

    for (int i = 0; i < nk; i++) {
        const int s = i & 1;
        if (i + 1 < nk) { load_stage(i + 1, s ^ 1); CP_WAIT1(); }
        else            { CP_WAIT0(); }
        __syncthreads();

        const float* As = smem + s * (ASZ + BSZ);
        const float* Bs = As + ASZ;

        #pragma unroll
        for (int kk = 0; kk < 4; kk++) {
            uint32_t af[4][4];
            #pragma unroll
            for (int mt = 0; mt < 4; mt++) {
                int r  = wm * 64 + mt * 16 + (lane >> 2);
                int kb = kk * 8 + (lane & 3);
                af[mt][0] = __float_as_uint(As[r * RS + kb]);
                af[mt][1] = __float_as_uint(As[(r + 8) * RS + kb]);
                af[mt][2] = __float_as_uint(As[r * RS + kb + 4]);
                af[mt][3] = __float_as_uint(As[(r + 8) * RS + kb + 4]);
            }
            #pragma unroll
            for (int nt = 0; nt < NT; nt++) {
                int cix = wn * WN + nt * 8 + (lane >> 2);
                uint32_t b0 = __float_as_uint(Bs[cix * RS + kk * 8 + (lane & 3)]);
                uint32_t b1 = __float_as_uint(Bs[cix * RS + kk * 8 + 4 + (lane & 3)]);
                #pragma unroll
                for (int mt = 0; mt < 4; mt++)
                    mma1688(acc[mt][nt], af[mt], b0, b1);
            }
        }
        __syncthreads();
    }

    #pragma unroll
    for (int mt = 0; mt < 4; mt++) {
        #pragma unroll
        for (int nt = 0; nt < NT; nt++) {
            int r0 = row0 + wm * 64 + mt * 16 + (lane >> 2);
            int c0 = col0 + wn * WN + nt * 8 + 2 * (lane & 3);
            #pragma unroll
            for (int half = 0; half < 2; half++) {
                int r = r0 + half * 8;
                float v0 = acc[mt][nt][2 * half + 0];
                float v1 = acc[mt][nt][2 * half + 1];
                if (EPI == 1) {
                    float m0 = __ldg(&mask[(size_t)bb * N + c0]);
                    float m1 = __ldg(&mask[(size_t)bb * N + c0 + 1]);
                    v0 = v0 * scale + (m0 - 1.0f) * 10000.0f;
                    v1 = v1 * scale + (m1 - 1.0f) * 10000.0f;
                } else {
                    if (bias) {
                        v0 += __ldg(&bias[c0]);
                        v1 += __ldg(&bias[c0 + 1]);
                    }
                }
                if (EPI == 2) {
                    v0 = 0.5f * v0 * (1.0f + erff(v0 * 0.70710678118654752f));
                    v1 = 0.5f * v1 * (1.0f + erff(v1 * 0.70710678118654752f));
                }
                if (EPI == 3) {
                    float2 rr = *reinterpret_cast<const float2*>(
                        residual + (size_t)r * ldc + c0);
                    v0 += rr.x; v1 += rr.y;
                }
                if (RND) { v0 = tf32r(v0); v1 = tf32r(v1); }
                float2 o; o.x = v0; o.y = v1;
                *reinterpret_cast<float2*>(C + (size_t)r * ldc + c0) = o;
            }
        }
    }
}

// ---------------- launch ----------------
extern "C" void kernel_launch(void* const* d_in, const int* in_sizes, int n_in,
                              void* d_out, int out_size) {
    const float* x   = (const float*)d_in[0];
    const float* am  = (const float*)d_in[1];
    const float* Wq  = (const float*)d_in[2];
    const float* bq  = (const float*)d_in[3];
    const float* Wk  = (const float*)d_in[4];
    const float* bk  = (const float*)d_in[5];
    const float* Wv  = (const float*)d_in[6];
    const float* bv  = (const float*)d_in[7];
    const float* Wo  = (const float*)d_in[8];
    const float* bo  = (const float*)d_in[9];
    const float* W1  = (const float*)d_in[10];
    const float* b1  = (const float*)d_in[11];
    const float* W2  = (const float*)d_in[12];
    const float* b2  = (const float*)d_in[13];
    const float* g1  = (const float*)d_in[14];
    const float* be1 = (const float*)d_in[15];
    const float* g2  = (const float*)d_in[16];
    const float* be2 = (const float*)d_in[17];
    float* out = (float*)d_out;

    float *h, *q, *k, *v, *vt, *ctx, *x2, *h2, *ff, *wr;
    cudaGetSymbolAddress((void**)&h,   g_h);
    cudaGetSymbolAddress((void**)&q,   g_q);
    cudaGetSymbolAddress((void**)&k,   g_k);
    cudaGetSymbolAddress((void**)&v,   g_v);
    cudaGetSymbolAddress((void**)&vt,  g_vt);
    cudaGetSymbolAddress((void**)&ctx, g_ctx);
    cudaGetSymbolAddress((void**)&x2,  g_x2);
    cudaGetSymbolAddress((void**)&h2,  g_h2);
    cudaGetSymbolAddress((void**)&ff,  g_ff);
    cudaGetSymbolAddress((void**)&wr,  g_wr);

    float* rWq = wr;
    float* rWk = wr + 1 * 1024 * 1024;
    float* rWv = wr + 2 * 1024 * 1024;
    float* rWo = wr + 3 * 1024 * 1024;
    float* rW1 = wr + 4 * 1024 * 1024;
    float* rW2 = wr + 8 * 1024 * 1024;

    const int SM128 = 2 * (128 * 36 + 128 * 36) * 4;
    cudaFuncSetAttribute(tc_gemm<128,0,true >, cudaFuncAttributeMaxDynamicSharedMemorySize, SM128);
    cudaFuncSetAttribute(tc_gemm<128,0,false>, cudaFuncAttributeMaxDynamicSharedMemorySize, SM128);
    cudaFuncSetAttribute(tc_gemm<128,2,true >, cudaFuncAttributeMaxDynamicSharedMemorySize, SM128);
    cudaFuncSetAttribute(tc_gemm<128,3,false>, cudaFuncAttributeMaxDynamicSharedMemorySize, SM128);
    cudaFuncSetAttribute(flash_kernel, cudaFuncAttributeMaxDynamicSharedMemorySize, FL_SMEM);

    dim3 blk(256);

    // weight rounding to tf32
    round_kernel<<<(1024*1024/4 + 255)/256, blk>>>(Wq, rWq, 1024*1024/4);
    round_kernel<<<(1024*1024/4 + 255)/256, blk>>>(Wk, rWk, 1024*1024/4);
    round_kernel<<<(1024*1024/4 + 255)/256, blk>>>(Wv, rWv, 1024*1024/4);
    round_kernel<<<(1024*1024/4 + 255)/256, blk>>>(Wo, rWo, 1024*1024/4);
    round_kernel<<<(4*1024*1024/4 + 255)/256, blk>>>(W1, rW1, 4*1024*1024/4);
    round_kernel<<<(4*1024*1024/4 + 255)/256, blk>>>(W2, rW2, 4*1024*1024/4);

    // h = LN1(x)
    ln_kernel<<<TOK_, blk>>>(x, g1, be1, h);

    // q/k/v
    tc_gemm<128,0,true ><<<dim3(HID_/128, TOK_/128, 1), blk, SM128>>>(TOK_, HID_, HID_,
        h, HID_, 0, 0,  rWq, HID_, 0, 0,  q, HID_, 0, 0,  bq, nullptr, nullptr, 0.f);
    tc_gemm<128,0,true ><<<dim3(HID_/128, TOK_/128, 1), blk, SM128>>>(TOK_, HID_, HID_,
        h, HID_, 0, 0,  rWk, HID_, 0, 0,  k, HID_, 0, 0,  bk, nullptr, nullptr, 0.f);
    tc_gemm<128,0,false><<<dim3(HID_/128, TOK_/128, 1), blk, SM128>>>(TOK_, HID_, HID_,
        h, HID_, 0, 0,  rWv, HID_, 0, 0,  v, HID_, 0, 0,  bv, nullptr, nullptr, 0.f);

    transpose_v_kernel<<<dim3(SS_/32, BB_*NH_*2), blk>>>(v, vt);

    // fused attention -> ctx (tf32-rounded)
    flash_kernel<<<dim3(SS_/128, BB_*NH_), blk, FL_SMEM>>>(q, k, vt, am, ctx);

    // x2 = x + ctx @ Wo^T + bo
    tc_gemm<128,3,false><<<dim3(HID_/128, TOK_/128, 1), blk, SM128>>>(TOK_, HID_, HID_,
        ctx, HID_, 0, 0,  rWo, HID_, 0, 0,  x2, HID_, 0, 0,  bo, x, nullptr, 0.f);

    // h2 = LN2(x2)
    ln_kernel<<<TOK_, blk>>>(x2, g2, be2, h2);

    // ff = gelu(h2 @ W1^T + b1)
    tc_gemm<128,2,true ><<<dim3(FF_/128, TOK_/128, 1), blk, SM128>>>(TOK_, FF_, HID_,
        h2, HID_, 0, 0,  rW1, HID_, 0, 0,  ff, FF_, 0, 0,  b1, nullptr, nullptr, 0.f);

    // out = x2 + ff @ W2^T + b2
    tc_gemm<128,3,false><<<dim3(HID_/128, TOK_/128, 1), blk, SM128>>>(TOK_, HID_, FF_,
        ff, FF_, 0, 0,  rW2, FF_, 0, 0,  out, HID_, 0, 0,  b2, x2, nullptr, 0.f);
}

// round 6
// speedup vs baseline: 3.7406x; 1.0553x over previous
#include <cuda_runtime.h>
#include <math.h>
#include <stdint.h>

#define BB_   2
#define SS_   2048
#define HID_  1024
#define NH_   16
#define HD_   64
#define FF_   4096
#define TOK_  (BB_*SS_)   // 4096

// ---------------- scratch ----------------
__device__ float g_h  [TOK_*HID_];
__device__ float g_q  [TOK_*HID_];
__device__ float g_k  [TOK_*HID_];
__device__ float g_v  [TOK_*HID_];
__device__ float g_vt [TOK_*HID_];                 // [B*H, 64, S]
__device__ float g_ctx[TOK_*HID_];
__device__ float g_x2 [TOK_*HID_];
__device__ float g_h2 [TOK_*HID_];
__device__ float g_ff [TOK_*FF_];
__device__ float g_wr [12*1024*1024];              // tf32-rounded weights

// ---------------- helpers ----------------
__device__ __forceinline__ float tf32r(float x) {
    float y;
    asm("cvt.rna.tf32.f32 %0, %1;" : "=f"(y) : "f"(x));
    return y;
}
__device__ __forceinline__ uint32_t smem_u32(const void* p) {
    uint32_t a;
    asm("{ .reg .u64 t; cvta.to.shared.u64 t, %1; cvt.u32.u64 %0, t; }" : "=r"(a) : "l"(p));
    return a;
}
#define CP16(dst, src) \
    asm volatile("cp.async.cg.shared.global [%0], [%1], 16;" :: "r"(dst), "l"(src) : "memory")
#define CP_COMMIT() asm volatile("cp.async.commit_group;" ::: "memory")
#define CP_WAIT1()  asm volatile("cp.async.wait_group 1;" ::: "memory")
#define CP_WAIT0()  asm volatile("cp.async.wait_group 0;" ::: "memory")

#define LDSM4(R0, R1, R2, R3, ADDR) \
    asm volatile("ldmatrix.sync.aligned.m8n8.x4.shared.b16 {%0,%1,%2,%3}, [%4];" \
        : "=r"(R0), "=r"(R1), "=r"(R2), "=r"(R3) : "r"(ADDR))

__device__ __forceinline__ void mma1688(float* c, const uint32_t* a, uint32_t b0, uint32_t b1) {
    asm volatile(
        "mma.sync.aligned.m16n8k8.row.col.f32.tf32.tf32.f32 "
        "{%0,%1,%2,%3}, {%4,%5,%6,%7}, {%8,%9}, {%0,%1,%2,%3};"
        : "+f"(c[0]), "+f"(c[1]), "+f"(c[2]), "+f"(c[3])
        : "r"(a[0]), "r"(a[1]), "r"(a[2]), "r"(a[3]), "r"(b0), "r"(b1));
}

// ---------------- fused weight rounding ----------------
// 4 x 1M-float tensors in one launch
__global__ void round4_kernel(const float* __restrict__ a, const float* __restrict__ b,
                              const float* __restrict__ c, const float* __restrict__ d,
                              float* __restrict__ oa, float* __restrict__ ob,
                              float* __restrict__ oc, float* __restrict__ od) {
    int i = blockIdx.x * blockDim.x + threadIdx.x;     // 0 .. 4*262144-1
    int seg = i >> 18, off = i & 262143;
    const float4* sp; float4* dp;
    if      (seg == 0) { sp = (const float4*)a; dp = (float4*)oa; }
    else if (seg == 1) { sp = (const float4*)b; dp = (float4*)ob; }
    else if (seg == 2) { sp = (const float4*)c; dp = (float4*)oc; }
    else               { sp = (const float4*)d; dp = (float4*)od; }
    float4 v = sp[off];
    v.x = tf32r(v.x); v.y = tf32r(v.y); v.z = tf32r(v.z); v.w = tf32r(v.w);
    dp[off] = v;
}
// 2 x 4M-float tensors in one launch
__global__ void round2_kernel(const float* __restrict__ a, const float* __restrict__ b,
                              float* __restrict__ oa, float* __restrict__ ob) {
    int i = blockIdx.x * blockDim.x + threadIdx.x;     // 0 .. 2*1048576-1
    int seg = i >> 20, off = i & 1048575;
    const float4* sp = seg ? (const float4*)b : (const float4*)a;
    float4*       dp = seg ? (float4*)ob      : (float4*)oa;
    float4 v = sp[off];
    v.x = tf32r(v.x); v.y = tf32r(v.y); v.z = tf32r(v.z); v.w = tf32r(v.w);
    dp[off] = v;
}

// ---------------- block reduction ----------------
template<bool MAX>
__device__ __forceinline__ float block_reduce_256(float v) {
    __shared__ float sh[8];
    int lane = threadIdx.x & 31, w = threadIdx.x >> 5;
    #pragma unroll
    for (int o = 16; o; o >>= 1) {
        float u = __shfl_xor_sync(0xffffffffu, v, o);
        v = MAX ? fmaxf(v, u) : v + u;
    }
    if (lane == 0) sh[w] = v;
    __syncthreads();
    if (w == 0) {
        v = sh[lane & 7];
        #pragma unroll
        for (int o = 4; o; o >>= 1) {
            float u = __shfl_xor_sync(0xffffffffu, v, o);
            v = MAX ? fmaxf(v, u) : v + u;
        }
        if (lane == 0) sh[0] = v;
    }
    __syncthreads();
    float r = sh[0];
    __syncthreads();
    return r;
}

// ---------------- LayerNorm (rounds output to tf32) ----------------
__global__ void ln_kernel(const float* __restrict__ x, const float* __restrict__ g,
                          const float* __restrict__ beta, float* __restrict__ out) {
    size_t base = (size_t)blockIdx.x * HID_;
    const float4* xp = reinterpret_cast<const float4*>(x + base);
    int t = threadIdx.x;
    float4 v = xp[t];
    float s = v.x + v.y + v.z + v.w;
    s = block_reduce_256<false>(s);
    float mean = s * (1.0f / HID_);
    float dx = v.x - mean, dy = v.y - mean, dz = v.z - mean, dw = v.w - mean;
    float q = dx*dx + dy*dy + dz*dz + dw*dw;
    q = block_reduce_256<false>(q);
    float r = rsqrtf(q * (1.0f / HID_) + 1e-5f);
    float4 gv = reinterpret_cast<const float4*>(g)[t];
    float4 bv = reinterpret_cast<const float4*>(beta)[t];
    float4 o;
    o.x = tf32r(dx * r * gv.x + bv.x);
    o.y = tf32r(dy * r * gv.y + bv.y);
    o.z = tf32r(dz * r * gv.z + bv.z);
    o.w = tf32r(dw * r * gv.w + bv.w);
    reinterpret_cast<float4*>(out + base)[t] = o;
}

// ---------------- transpose V (rounds output) ----------------
__global__ void transpose_v_kernel(const float* __restrict__ v, float* __restrict__ vt) {
    __shared__ float t[32][33];
    int bz = blockIdx.y;
    int b = bz / (NH_ * 2);
    int rem = bz % (NH_ * 2);
    int h = rem >> 1;
    int d0 = (rem & 1) * 32;
    int s0 = blockIdx.x * 32;
    int tx = threadIdx.x & 31, ty = threadIdx.x >> 5;
    #pragma unroll
    for (int i = 0; i < 32; i += 8)
        t[ty + i][tx] = v[((size_t)b * SS_ + s0 + ty + i) * HID_ + h * 64 + d0 + tx];
    __syncthreads();
    #pragma unroll
    for (int i = 0; i < 32; i += 8)
        vt[(((size_t)b * NH_ + h) * 64 + d0 + ty + i) * SS_ + s0 + tx] = tf32r(t[tx][ty + i]);
}

// ---------------- fused flash attention (ldmatrix fragments) ----------------
#define FRS 68
#define OFF_Q  0
#define OFF_K  (128*FRS)
#define OFF_V  (OFF_K + 2*64*FRS)
#define OFF_P  (OFF_V + 2*64*FRS)
#define OFF_MD (OFF_P + 128*FRS)
#define OFF_MX (OFF_MD + 2048)
#define OFF_SU (OFF_MX + 512)
#define FL_SMEM ((OFF_SU + 512) * 4)

__global__ __launch_bounds__(256, 1) void flash_kernel(
    const float* __restrict__ q, const float* __restrict__ k,
    const float* __restrict__ vt, const float* __restrict__ am,
    float* __restrict__ ctx)
{
    extern __shared__ float sm[];
    float* Ps   = sm + OFF_P;
    float* Madd = sm + OFF_MD;
    float* Pmax = sm + OFF_MX;
    float* Psum = sm + OFF_SU;

    const int tid = threadIdx.x, lane = tid & 31, wid = tid >> 5;
    const int wm = wid >> 2, wn = wid & 3;
    const int seg = lane >> 3, l8 = lane & 7;
    const int qt = blockIdx.x, bh = blockIdx.y;
    const int bb = bh >> 4, hh = bh & 15;
    const int q0 = qt * 128;

    const float* Qg = q  + ((size_t)bb * SS_ + q0) * HID_ + hh * 64;
    const float* Kg = k  + (size_t)bb * SS_ * HID_ + hh * 64;
    const float* Vg = vt + (size_t)bh * 64 * SS_;

    const uint32_t sb = smem_u32(sm);
    const uint32_t sQ = sb + OFF_Q * 4, sP = sb + OFF_P * 4;

    // Q tile (128 x 64) -> smem
    #pragma unroll
    for (int u = 0; u < 8; u++) {
        int idx = tid + u * 256;
        int r = idx >> 4, c4 = (idx & 15) << 2;
        CP16(sQ + (uint32_t)((r * FRS + c4) * 4), Qg + (size_t)r * HID_ + c4);
    }
    CP_COMMIT();
    #pragma unroll
    for (int u = 0; u < 8; u++) {
        int i = tid + u * 256;
        Madd[i] = (__ldg(&am[(size_t)bb * SS_ + i]) - 1.0f) * 10000.0f;
    }

    auto load_kv = [&](int j, int s) {
        const int j0 = j * 64;
        uint32_t kb = sb + (uint32_t)((OFF_K + s * 64 * FRS) * 4);
        uint32_t vb = sb + (uint32_t)((OFF_V + s * 64 * FRS) * 4);
        #pragma unroll
        for (int u = 0; u < 4; u++) {
            int idx = tid + u * 256;
            int r = idx >> 4, c4 = (idx & 15) << 2;
            CP16(kb + (uint32_t)((r * FRS + c4) * 4), Kg + (size_t)(j0 + r) * HID_ + c4);
        }
        #pragma unroll
        for (int u = 0; u < 4; u++) {
            int idx = tid + u * 256;
            int r = idx >> 4, c4 = (idx & 15) << 2;
            CP16(vb + (uint32_t)((r * FRS + c4) * 4), Vg + (size_t)r * SS_ + j0 + c4);
        }
        CP_COMMIT();
    };
    load_kv(0, 0);

    float ctxa[4][2][4] = {};
    float mrow[4][2], lrow[4][2];
    #pragma unroll
    for (int mt = 0; mt < 4; mt++) {
        mrow[mt][0] = -1e30f; mrow[mt][1] = -1e30f;
        lrow[mt][0] = 0.f;    lrow[mt][1] = 0.f;
    }

    const int IT = SS_ / 64;
    for (int j = 0; j < IT; j++) {
        const int s = j & 1;
        __syncthreads();
        if (j + 1 < IT) { load_kv(j + 1, s ^ 1); CP_WAIT1(); }
        else            { CP_WAIT0(); }
        __syncthreads();

        // ---- S = Q @ K^T ----
        float sacc[4][2][4] = {};
        const uint32_t sKs = sb + (uint32_t)((OFF_K + s * 64 * FRS) * 4);
        #pragma unroll
        for (int kk = 0; kk < 8; kk++) {
            uint32_t af[4][4];
            #pragma unroll
            for (int mt = 0; mt < 4; mt++) {
                int rr = wm * 64 + mt * 16 + ((seg & 1) << 3) + l8;
                int cc = kk * 8 + ((seg >> 1) << 2);
                LDSM4(af[mt][0], af[mt][1], af[mt][2], af[mt][3],
                      sQ + (uint32_t)((rr * FRS + cc) * 4));
            }
            uint32_t bf[2][2];
            {
                int nn = wn * 16 + ((seg >> 1) << 3) + l8;
                int cc = kk * 8 + ((seg & 1) << 2);
                LDSM4(bf[0][0], bf[0][1], bf[1][0], bf[1][1],
                      sKs + (uint32_t)((nn * FRS + cc) * 4));
            }
            #pragma unroll
            for (int nt = 0; nt < 2; nt++)
                #pragma unroll
                for (int mt = 0; mt < 4; mt++)
                    mma1688(sacc[mt][nt], af[mt], bf[nt][0], bf[nt][1]);
        }

        // ---- scale + mask, local row max ----
        const int j0 = j * 64;
        float lmax[4][2];
        #pragma unroll
        for (int mt = 0; mt < 4; mt++) { lmax[mt][0] = -1e30f; lmax[mt][1] = -1e30f; }
        #pragma unroll
        for (int nt = 0; nt < 2; nt++) {
            int cl = wn * 16 + nt * 8 + 2 * (lane & 3);
            float2 md = *reinterpret_cast<const float2*>(&Madd[j0 + cl]);
            #pragma unroll
            for (int mt = 0; mt < 4; mt++) {
                sacc[mt][nt][0] = sacc[mt][nt][0] * 0.125f + md.x;
                sacc[mt][nt][1] = sacc[mt][nt][1] * 0.125f + md.y;
                sacc[mt][nt][2] = sacc[mt][nt][2] * 0.125f + md.x;
                sacc[mt][nt][3] = sacc[mt][nt][3] * 0.125f + md.y;
                lmax[mt][0] = fmaxf(lmax[mt][0], fmaxf(sacc[mt][nt][0], sacc[mt][nt][1]));
                lmax[mt][1] = fmaxf(lmax[mt][1], fmaxf(sacc[mt][nt][2], sacc[mt][nt][3]));
            }
        }
        #pragma unroll
        for (int mt = 0; mt < 4; mt++)
            #pragma unroll
            for (int h2 = 0; h2 < 2; h2++) {
                float v = lmax[mt][h2];
                v = fmaxf(v, __shfl_xor_sync(0xffffffffu, v, 1));
                v = fmaxf(v, __shfl_xor_sync(0xffffffffu, v, 2));
                lmax[mt][h2] = v;
            }
        if ((lane & 3) == 0) {
            #pragma unroll
            for (int mt = 0; mt < 4; mt++)
                #pragma unroll
                for (int h2 = 0; h2 < 2; h2++) {
                    int row = wm * 64 + mt * 16 + h2 * 8 + (lane >> 2);
                    Pmax[wn * 128 + row] = lmax[mt][h2];
                }
        }
        __syncthreads();

        // ---- m update, alpha, P = exp, local sums ----
        float alpha[4][2], lsum[4][2];
        #pragma unroll
        for (int mt = 0; mt < 4; mt++)
            #pragma unroll
            for (int h2 = 0; h2 < 2; h2++) {
                int row = wm * 64 + mt * 16 + h2 * 8 + (lane >> 2);
                float tm = fmaxf(fmaxf(Pmax[row], Pmax[128 + row]),
                                 fmaxf(Pmax[256 + row], Pmax[384 + row]));
                float mo = mrow[mt][h2];
                float mn = fmaxf(mo, tm);
                mrow[mt][h2]  = mn;
                alpha[mt][h2] = __expf(mo - mn);
                lsum[mt][h2]  = 0.f;
            }
        #pragma unroll
        for (int nt = 0; nt < 2; nt++) {
            int cl = wn * 16 + nt * 8 + 2 * (lane & 3);
            #pragma unroll
            for (int mt = 0; mt < 4; mt++)
                #pragma unroll
                for (int h2 = 0; h2 < 2; h2++) {
                    float p0 = __expf(sacc[mt][nt][2 * h2 + 0] - mrow[mt][h2]);
                    float p1 = __expf(sacc[mt][nt][2 * h2 + 1] - mrow[mt][h2]);
                    lsum[mt][h2] += p0 + p1;
                    int row = wm * 64 + mt * 16 + h2 * 8 + (lane >> 2);
                    float2 pp; pp.x = tf32r(p0); pp.y = tf32r(p1);
                    *reinterpret_cast<float2*>(&Ps[row * FRS + cl]) = pp;
                }
        }
        #pragma unroll
        for (int mt = 0; mt < 4; mt++)
            #pragma unroll
            for (int h2 = 0; h2 < 2; h2++) {
                float v = lsum[mt][h2];
                v += __shfl_xor_sync(0xffffffffu, v, 1);
                v += __shfl_xor_sync(0xffffffffu, v, 2);
                lsum[mt][h2] = v;
            }
        if ((lane & 3) == 0) {
            #pragma unroll
            for (int mt = 0; mt < 4; mt++)
                #pragma unroll
                for (int h2 = 0; h2 < 2; h2++) {
                    int row = wm * 64 + mt * 16 + h2 * 8 + (lane >> 2);
                    Psum[wn * 128 + row] = lsum[mt][h2];
                }
        }
        __syncthreads();
        #pragma unroll
        for (int mt = 0; mt < 4; mt++)
            #pragma unroll
            for (int h2 = 0; h2 < 2; h2++) {
                int row = wm * 64 + mt * 16 + h2 * 8 + (lane >> 2);
                float ts = Psum[row] + Psum[128 + row] + Psum[256 + row] + Psum[384 + row];
                lrow[mt][h2] = lrow[mt][h2] * alpha[mt][h2] + ts;
                #pragma unroll
                for (int nt = 0; nt < 2; nt++) {
                    ctxa[mt][nt][2 * h2 + 0] *= alpha[mt][h2];
                    ctxa[mt][nt][2 * h2 + 1] *= alpha[mt][h2];
                }
            }

        // ---- ctx += P @ V^T ----
        const uint32_t sVs = sb + (uint32_t)((OFF_V + s * 64 * FRS) * 4);
        #pragma unroll
        for (int kk = 0; kk < 8; kk++) {
            uint32_t af[4][4];
            #pragma unroll
            for (int mt = 0; mt < 4; mt++) {
                int rr = wm * 64 + mt * 16 + ((seg & 1) << 3) + l8;
                int cc = kk * 8 + ((seg >> 1) << 2);
                LDSM4(af[mt][0], af[mt][1], af[mt][2], af[mt][3],
                      sP + (uint32_t)((rr * FRS + cc) * 4));
            }
            uint32_t bf[2][2];
            {
                int nn = wn * 16 + ((seg >> 1) << 3) + l8;
                int cc = kk * 8 + ((seg & 1) << 2);
                LDSM4(bf[0][0], bf[0][1], bf[1][0], bf[1][1],
                      sVs + (uint32_t)((nn * FRS + cc) * 4));
            }
            #pragma unroll
            for (int nt = 0; nt < 2; nt++)
                #pragma unroll
                for (int mt = 0; mt < 4; mt++)
                    mma1688(ctxa[mt][nt], af[mt], bf[nt][0], bf[nt][1]);
        }
    }

    // ---- finalize ----
    #pragma unroll
    for (int mt = 0; mt < 4; mt++)
        #pragma unroll
        for (int h2 = 0; h2 < 2; h2++) {
            int row = wm * 64 + mt * 16 + h2 * 8 + (lane >> 2);
            float inv = 1.0f / lrow[mt][h2];
            #pragma unroll
            for (int nt = 0; nt < 2; nt++) {
                int cl = wn * 16 + nt * 8 + 2 * (lane & 3);
                float2 o;
                o.x = tf32r(ctxa[mt][nt][2 * h2 + 0] * inv);
                o.y = tf32r(ctxa[mt][nt][2 * h2 + 1] * inv);
                *reinterpret_cast<float2*>(
                    ctx + ((size_t)bb * SS_ + q0 + row) * HID_ + hh * 64 + cl) = o;
            }
        }
}

// ---------------- tf32 mma.sync GEMM (ldmatrix fragments) ----------------
template<int BN, int EPI, bool RND>
__global__ __launch_bounds__(256, 2) void tc_gemm(
    int M, int N, int K,
    const float* __restrict__ A,  int lda, long long sAb, long long sAh,
    const float* __restrict__ Bm, int ldb, long long sBb, long long sBh,
    float* __restrict__ C,        int ldc, long long sCb, long long sCh,
    const float* __restrict__ bias, const float* __restrict__ residual,
    const float* __restrict__ mask, float scale)
{
    constexpr int RS  = 36;
    constexpr int ASZ = 128 * RS;
    constexpr int BSZ = BN * RS;
    constexpr int WN  = BN / 4;
    constexpr int NT  = WN / 8;

    extern __shared__ __align__(16) float smem[];

    const int tid  = threadIdx.x;
    const int wid  = tid >> 5, lane = tid & 31;
    const int wm   = wid >> 2, wn = wid & 3;
    const int seg  = lane >> 3, l8 = lane & 7;
    const int bz   = blockIdx.z, bb = bz >> 4, hh = bz & 15;
    A  += bb * sAb + hh * sAh;
    Bm += bb * sBb + hh * sBh;
    C  += bb * sCb + hh * sCh;
    const int row0 = blockIdx.y * 128;
    const int col0 = blockIdx.x * BN;

    const uint32_t sbase = smem_u32(smem);

    float acc[4][NT][4];
    #pragma unroll
    for (int i = 0; i < 4; i++)
        #pragma unroll
        for (int j = 0; j < NT; j++)
            #pragma unroll
            for (int e = 0; e < 4; e++) acc[i][j][e] = 0.0f;

    const int nk = K >> 5;

    auto load_stage = [&](int i, int s) {
        const int k0 = i << 5;
        uint32_t abase = sbase + (uint32_t)(s * (ASZ + BSZ)) * 4u;
        uint32_t bbase = abase + (uint32_t)ASZ * 4u;
        #pragma unroll
        for (int u = 0; u < 4; u++) {
            int idx = tid + u * 256;
            int r = idx >> 3, c4 = (idx & 7) << 2;
            CP16(abase + (uint32_t)(r * RS + c4) * 4u,
                 A + (size_t)(row0 + r) * lda + k0 + c4);
        }
        #pragma unroll
        for (int u = 0; u < BN / 32; u++) {
            int idx = tid + u * 256;
            int r = idx >> 3, c4 = (idx & 7) << 2;
            CP16(bbase + (uint32_t)(r * RS + c4) * 4u,
                 Bm + (size_t)(col0 + r) * ldb + k0 + c4);
        }
        CP_COMMIT();
    };

    load_stage(0, 0);

    for (int i = 0; i < nk; i++) {
        const int s = i & 1;
        if (i + 1 < nk) { load_stage(i + 1, s ^ 1); CP_WAIT1(); }
        else            { CP_WAIT0(); }
        __syncthreads();

        const uint32_t sAs = sbase + (uint32_t)(s * (ASZ + BSZ)) * 4u;
        const uint32_t sBs = sAs + (uint32_t)ASZ * 4u;

        #pragma unroll
        for (int kk = 0; kk < 4; kk++) {
            uint32_t af[4][4];
            #pragma unroll
            for (int mt = 0; mt < 4; mt++) {
                int rr = wm * 64 + mt * 16 + ((seg & 1) << 3) + l8;
                int cc = kk * 8 + ((seg >> 1) << 2);
                LDSM4(af[mt][0], af[mt][1], af[mt][2], af[mt][3],
                      sAs + (uint32_t)((rr * RS + cc) * 4));
            }
            uint32_t bf[NT][2];
            #pragma unroll
            for (int ntp = 0; ntp < NT / 2; ntp++) {
                int nn = wn * WN + ntp * 16 + ((seg >> 1) << 3) + l8;
                int cc = kk * 8 + ((seg & 1) << 2);
                LDSM4(bf[2*ntp][0], bf[2*ntp][1], bf[2*ntp+1][0], bf[2*ntp+1][1],
                      sBs + (uint32_t)((nn * RS + cc) * 4));
            }
            #pragma unroll
            for (int nt = 0; nt < NT; nt++)
                #pragma unroll
                for (int mt = 0; mt < 4; mt++)
                    mma1688(acc[mt][nt], af[mt], bf[nt][0], bf[nt][1]);
        }
        __syncthreads();
    }

    #pragma unroll
    for (int mt = 0; mt < 4; mt++) {
        #pragma unroll
        for (int nt = 0; nt < NT; nt++) {
            int r0 = row0 + wm * 64 + mt * 16 + (lane >> 2);
            int c0 = col0 + wn * WN + nt * 8 + 2 * (lane & 3);
            #pragma unroll
            for (int half = 0; half < 2; half++) {
                int r = r0 + half * 8;
                float v0 = acc[mt][nt][2 * half + 0];
                float v1 = acc[mt][nt][2 * half + 1];
                if (EPI == 1) {
                    float m0 = __ldg(&mask[(size_t)bb * N + c0]);
                    float m1 = __ldg(&mask[(size_t)bb * N + c0 + 1]);
                    v0 = v0 * scale + (m0 - 1.0f) * 10000.0f;
                    v1 = v1 * scale + (m1 - 1.0f) * 10000.0f;
                } else {
                    if (bias) {
                        v0 += __ldg(&bias[c0]);
                        v1 += __ldg(&bias[c0 + 1]);
                    }
                }
                if (EPI == 2) {
                    v0 = 0.5f * v0 * (1.0f + erff(v0 * 0.70710678118654752f));
                    v1 = 0.5f * v1 * (1.0f + erff(v1 * 0.70710678118654752f));
                }
                if (EPI == 3) {
                    float2 rr = *reinterpret_cast<const float2*>(
                        residual + (size_t)r * ldc + c0);
                    v0 += rr.x; v1 += rr.y;
                }
                if (RND) { v0 = tf32r(v0); v1 = tf32r(v1); }
                float2 o; o.x = v0; o.y = v1;
                *reinterpret_cast<float2*>(C + (size_t)r * ldc + c0) = o;
            }
        }
    }
}

// ---------------- launch ----------------
extern "C" void kernel_launch(void* const* d_in, const int* in_sizes, int n_in,
                              void* d_out, int out_size) {
    const float* x   = (const float*)d_in[0];
    const float* am  = (const float*)d_in[1];
    const float* Wq  = (const float*)d_in[2];
    const float* bq  = (const float*)d_in[3];
    const float* Wk  = (const float*)d_in[4];
    const float* bk  = (const float*)d_in[5];
    const float* Wv  = (const float*)d_in[6];
    const float* bv  = (const float*)d_in[7];
    const float* Wo  = (const float*)d_in[8];
    const float* bo  = (const float*)d_in[9];
    const float* W1  = (const float*)d_in[10];
    const float* b1  = (const float*)d_in[11];
    const float* W2  = (const float*)d_in[12];
    const float* b2  = (const float*)d_in[13];
    const float* g1  = (const float*)d_in[14];
    const float* be1 = (const float*)d_in[15];
    const float* g2  = (const float*)d_in[16];
    const float* be2 = (const float*)d_in[17];
    float* out = (float*)d_out;

    float *h, *q, *k, *v, *vt, *ctx, *x2, *h2, *ff, *wr;
    cudaGetSymbolAddress((void**)&h,   g_h);
    cudaGetSymbolAddress((void**)&q,   g_q);
    cudaGetSymbolAddress((void**)&k,   g_k);
    cudaGetSymbolAddress((void**)&v,   g_v);
    cudaGetSymbolAddress((void**)&vt,  g_vt);
    cudaGetSymbolAddress((void**)&ctx, g_ctx);
    cudaGetSymbolAddress((void**)&x2,  g_x2);
    cudaGetSymbolAddress((void**)&h2,  g_h2);
    cudaGetSymbolAddress((void**)&ff,  g_ff);
    cudaGetSymbolAddress((void**)&wr,  g_wr);

    float* rWq = wr;
    float* rWk = wr + 1 * 1024 * 1024;
    float* rWv = wr + 2 * 1024 * 1024;
    float* rWo = wr + 3 * 1024 * 1024;
    float* rW1 = wr + 4 * 1024 * 1024;
    float* rW2 = wr + 8 * 1024 * 1024;

    const int SM128 = 2 * (128 * 36 + 128 * 36) * 4;
    cudaFuncSetAttribute(tc_gemm<128,0,true >, cudaFuncAttributeMaxDynamicSharedMemorySize, SM128);
    cudaFuncSetAttribute(tc_gemm<128,0,false>, cudaFuncAttributeMaxDynamicSharedMemorySize, SM128);
    cudaFuncSetAttribute(tc_gemm<128,2,true >, cudaFuncAttributeMaxDynamicSharedMemorySize, SM128);
    cudaFuncSetAttribute(tc_gemm<128,3,false>, cudaFuncAttributeMaxDynamicSharedMemorySize, SM128);
    cudaFuncSetAttribute(flash_kernel, cudaFuncAttributeMaxDynamicSharedMemorySize, FL_SMEM);

    dim3 blk(256);

    // weight rounding to tf32 (2 launches)
    round4_kernel<<<4096, blk>>>(Wq, Wk, Wv, Wo, rWq, rWk, rWv, rWo);
    round2_kernel<<<8192, blk>>>(W1, W2, rW1, rW2);

    // h = LN1(x)
    ln_kernel<<<TOK_, blk>>>(x, g1, be1, h);

    // q/k/v
    tc_gemm<128,0,true ><<<dim3(HID_/128, TOK_/128, 1), blk, SM128>>>(TOK_, HID_, HID_,
        h, HID_, 0, 0,  rWq, HID_, 0, 0,  q, HID_, 0, 0,  bq, nullptr, nullptr, 0.f);
    tc_gemm<128,0,true ><<<dim3(HID_/128, TOK_/128, 1), blk, SM128>>>(TOK_, HID_, HID_,
        h, HID_, 0, 0,  rWk, HID_, 0, 0,  k, HID_, 0, 0,  bk, nullptr, nullptr, 0.f);
    tc_gemm<128,0,false><<<dim3(HID_/128, TOK_/128, 1), blk, SM128>>>(TOK_, HID_, HID_,
        h, HID_, 0, 0,  rWv, HID_, 0, 0,  v, HID_, 0, 0,  bv, nullptr, nullptr, 0.f);

    transpose_v_kernel<<<dim3(SS_/32, BB_*NH_*2), blk>>>(v, vt);

    // fused attention -> ctx (tf32-rounded)
    flash_kernel<<<dim3(SS_/128, BB_*NH_), blk, FL_SMEM>>>(q, k, vt, am, ctx);

    // x2 = x + ctx @ Wo^T + bo
    tc_gemm<128,3,false><<<dim3(HID_/128, TOK_/128, 1), blk, SM128>>>(TOK_, HID_, HID_,
        ctx, HID_, 0, 0,  rWo, HID_, 0, 0,  x2, HID_, 0, 0,  bo, x, nullptr, 0.f);

    // h2 = LN2(x2)
    ln_kernel<<<TOK_, blk>>>(x2, g2, be2, h2);

    // ff = gelu(h2 @ W1^T + b1)
    tc_gemm<128,2,true ><<<dim3(FF_/128, TOK_/128, 1), blk, SM128>>>(TOK_, FF_, HID_,
        h2, HID_, 0, 0,  rW1, HID_, 0, 0,  ff, FF_, 0, 0,  b1, nullptr, nullptr, 0.f);

    // out = x2 + ff @ W2^T + b2
    tc_gemm<128,3,false><<<dim3(HID_/128, TOK_/128, 1), blk, SM128>>>(TOK_, HID_, FF_,
        ff, FF_, 0, 0,  rW2, FF_, 0, 0,  out, HID_, 0, 0,  b2, x2, nullptr, 0.f);
}

// round 7
// speedup vs baseline: 3.8076x; 1.0179x over previous
#include <cuda_runtime.h>
#include <math.h>
#include <stdint.h>

#define BB_   2
#define SS_   2048
#define HID_  1024
#define NH_   16
#define HD_   64
#define FF_   4096
#define TOK_  (BB_*SS_)   // 4096
#define QKVLD 3072

// ---------------- scratch ----------------
__device__ float g_h  [TOK_*HID_];
__device__ float g_qkv[TOK_*3*HID_];               // [TOK, 3072] = q|k|v
__device__ float g_vt [TOK_*HID_];                 // [B*H, 64, S]
__device__ float g_ctx[TOK_*HID_];
__device__ float g_x2 [TOK_*HID_];
__device__ float g_h2 [TOK_*HID_];
__device__ float g_ff [TOK_*FF_];
__device__ float g_wr [12*1024*1024];              // tf32-rounded weights (q|k|v|o|W1|W2)
__device__ float g_bqkv[3*HID_];                   // packed qkv bias

// ---------------- helpers ----------------
__device__ __forceinline__ float tf32r(float x) {
    float y;
    asm("cvt.rna.tf32.f32 %0, %1;" : "=f"(y) : "f"(x));
    return y;
}
__device__ __forceinline__ uint32_t smem_u32(const void* p) {
    uint32_t a;
    asm("{ .reg .u64 t; cvta.to.shared.u64 t, %1; cvt.u32.u64 %0, t; }" : "=r"(a) : "l"(p));
    return a;
}
#define CP16(dst, src) \
    asm volatile("cp.async.cg.shared.global [%0], [%1], 16;" :: "r"(dst), "l"(src) : "memory")
#define CP_COMMIT() asm volatile("cp.async.commit_group;" ::: "memory")
#define CP_WAIT1()  asm volatile("cp.async.wait_group 1;" ::: "memory")
#define CP_WAIT0()  asm volatile("cp.async.wait_group 0;" ::: "memory")

#define LDSM4(R0, R1, R2, R3, ADDR) \
    asm volatile("ldmatrix.sync.aligned.m8n8.x4.shared.b16 {%0,%1,%2,%3}, [%4];" \
        : "=r"(R0), "=r"(R1), "=r"(R2), "=r"(R3) : "r"(ADDR))

__device__ __forceinline__ void mma1688(float* c, const uint32_t* a, uint32_t b0, uint32_t b1) {
    asm volatile(
        "mma.sync.aligned.m16n8k8.row.col.f32.tf32.tf32.f32 "
        "{%0,%1,%2,%3}, {%4,%5,%6,%7}, {%8,%9}, {%0,%1,%2,%3};"
        : "+f"(c[0]), "+f"(c[1]), "+f"(c[2]), "+f"(c[3])
        : "r"(a[0]), "r"(a[1]), "r"(a[2]), "r"(a[3]), "r"(b0), "r"(b1));
}

// ---------------- bias pack (q|k|v -> contiguous) ----------------
__global__ void pack_bias_kernel(const float* __restrict__ a, const float* __restrict__ b,
                                 const float* __restrict__ c, float* __restrict__ o) {
    int i = blockIdx.x * blockDim.x + threadIdx.x;
    if (i < HID_)            o[i] = a[i];
    else if (i < 2 * HID_)   o[i] = b[i - HID_];
    else if (i < 3 * HID_)   o[i] = c[i - 2 * HID_];
}

// ---------------- fused weight rounding ----------------
__global__ void round4_kernel(const float* __restrict__ a, const float* __restrict__ b,
                              const float* __restrict__ c, const float* __restrict__ d,
                              float* __restrict__ oa, float* __restrict__ ob,
                              float* __restrict__ oc, float* __restrict__ od) {
    int i = blockIdx.x * blockDim.x + threadIdx.x;
    int seg = i >> 18, off = i & 262143;
    const float4* sp; float4* dp;
    if      (seg == 0) { sp = (const float4*)a; dp = (float4*)oa; }
    else if (seg == 1) { sp = (const float4*)b; dp = (float4*)ob; }
    else if (seg == 2) { sp = (const float4*)c; dp = (float4*)oc; }
    else               { sp = (const float4*)d; dp = (float4*)od; }
    float4 v = sp[off];
    v.x = tf32r(v.x); v.y = tf32r(v.y); v.z = tf32r(v.z); v.w = tf32r(v.w);
    dp[off] = v;
}
__global__ void round2_kernel(const float* __restrict__ a, const float* __restrict__ b,
                              float* __restrict__ oa, float* __restrict__ ob) {
    int i = blockIdx.x * blockDim.x + threadIdx.x;
    int seg = i >> 20, off = i & 1048575;
    const float4* sp = seg ? (const float4*)b : (const float4*)a;
    float4*       dp = seg ? (float4*)ob      : (float4*)oa;
    float4 v = sp[off];
    v.x = tf32r(v.x); v.y = tf32r(v.y); v.z = tf32r(v.z); v.w = tf32r(v.w);
    dp[off] = v;
}

// ---------------- block reduction ----------------
template<bool MAX>
__device__ __forceinline__ float block_reduce_256(float v) {
    __shared__ float sh[8];
    int lane = threadIdx.x & 31, w = threadIdx.x >> 5;
    #pragma unroll
    for (int o = 16; o; o >>= 1) {
        float u = __shfl_xor_sync(0xffffffffu, v, o);
        v = MAX ? fmaxf(v, u) : v + u;
    }
    if (lane == 0) sh[w] = v;
    __syncthreads();
    if (w == 0) {
        v = sh[lane & 7];
        #pragma unroll
        for (int o = 4; o; o >>= 1) {
            float u = __shfl_xor_sync(0xffffffffu, v, o);
            v = MAX ? fmaxf(v, u) : v + u;
        }
        if (lane == 0) sh[0] = v;
    }
    __syncthreads();
    float r = sh[0];
    __syncthreads();
    return r;
}

// ---------------- LayerNorm (rounds output to tf32) ----------------
__global__ void ln_kernel(const float* __restrict__ x, const float* __restrict__ g,
                          const float* __restrict__ beta, float* __restrict__ out) {
    size_t base = (size_t)blockIdx.x * HID_;
    const float4* xp = reinterpret_cast<const float4*>(x + base);
    int t = threadIdx.x;
    float4 v = xp[t];
    float s = v.x + v.y + v.z + v.w;
    s = block_reduce_256<false>(s);
    float mean = s * (1.0f / HID_);
    float dx = v.x - mean, dy = v.y - mean, dz = v.z - mean, dw = v.w - mean;
    float q = dx*dx + dy*dy + dz*dz + dw*dw;
    q = block_reduce_256<false>(q);
    float r = rsqrtf(q * (1.0f / HID_) + 1e-5f);
    float4 gv = reinterpret_cast<const float4*>(g)[t];
    float4 bv = reinterpret_cast<const float4*>(beta)[t];
    float4 o;
    o.x = tf32r(dx * r * gv.x + bv.x);
    o.y = tf32r(dy * r * gv.y + bv.y);
    o.z = tf32r(dz * r * gv.z + bv.z);
    o.w = tf32r(dw * r * gv.w + bv.w);
    reinterpret_cast<float4*>(out + base)[t] = o;
}

// ---------------- transpose V (from qkv buffer, rounds output) ----------------
__global__ void transpose_v_kernel(const float* __restrict__ qkv, float* __restrict__ vt) {
    __shared__ float t[32][33];
    int bz = blockIdx.y;
    int b = bz / (NH_ * 2);
    int rem = bz % (NH_ * 2);
    int h = rem >> 1;
    int d0 = (rem & 1) * 32;
    int s0 = blockIdx.x * 32;
    int tx = threadIdx.x & 31, ty = threadIdx.x >> 5;
    #pragma unroll
    for (int i = 0; i < 32; i += 8)
        t[ty + i][tx] = qkv[((size_t)b * SS_ + s0 + ty + i) * QKVLD + 2 * HID_ + h * 64 + d0 + tx];
    __syncthreads();
    #pragma unroll
    for (int i = 0; i < 32; i += 8)
        vt[(((size_t)b * NH_ + h) * 64 + d0 + ty + i) * SS_ + s0 + tx] = tf32r(t[tx][ty + i]);
}

// ---------------- fused flash attention ----------------
#define FRS 68
#define OFF_Q  0
#define OFF_K  (128*FRS)
#define OFF_V  (OFF_K + 2*64*FRS)
#define OFF_P  (OFF_V + 2*64*FRS)
#define OFF_MD (OFF_P + 128*FRS)
#define OFF_MX (OFF_MD + 2048)
#define OFF_SU (OFF_MX + 512)
#define FL_SMEM ((OFF_SU + 512) * 4)

__global__ __launch_bounds__(256, 1) void flash_kernel(
    const float* __restrict__ qkv, const float* __restrict__ vt,
    const float* __restrict__ am, float* __restrict__ ctx)
{
    extern __shared__ float sm[];
    float* Ps   = sm + OFF_P;
    float* Madd = sm + OFF_MD;
    float* Pmax = sm + OFF_MX;
    float* Psum = sm + OFF_SU;

    const int tid = threadIdx.x, lane = tid & 31, wid = tid >> 5;
    const int wm = wid >> 2, wn = wid & 3;
    const int seg = lane >> 3, l8 = lane & 7;
    const int qt = blockIdx.x, bh = blockIdx.y;
    const int bb = bh >> 4, hh = bh & 15;
    const int q0 = qt * 128;

    const float* Qg = qkv + ((size_t)bb * SS_ + q0) * QKVLD + hh * 64;
    const float* Kg = qkv + (size_t)bb * SS_ * QKVLD + HID_ + hh * 64;
    const float* Vg = vt + (size_t)bh * 64 * SS_;

    const uint32_t sb = smem_u32(sm);
    const uint32_t sQ = sb + OFF_Q * 4, sP = sb + OFF_P * 4;

    #pragma unroll
    for (int u = 0; u < 8; u++) {
        int idx = tid + u * 256;
        int r = idx >> 4, c4 = (idx & 15) << 2;
        CP16(sQ + (uint32_t)((r * FRS + c4) * 4), Qg + (size_t)r * QKVLD + c4);
    }
    CP_COMMIT();
    #pragma unroll
    for (int u = 0; u < 8; u++) {
        int i = tid + u * 256;
        Madd[i] = (__ldg(&am[(size_t)bb * SS_ + i]) - 1.0f) * 10000.0f;
    }

    auto load_kv = [&](int j, int s) {
        const int j0 = j * 64;
        uint32_t kb = sb + (uint32_t)((OFF_K + s * 64 * FRS) * 4);
        uint32_t vb = sb + (uint32_t)((OFF_V + s * 64 * FRS) * 4);
        #pragma unroll
        for (int u = 0; u < 4; u++) {
            int idx = tid + u * 256;
            int r = idx >> 4, c4 = (idx & 15) << 2;
            CP16(kb + (uint32_t)((r * FRS + c4) * 4), Kg + (size_t)(j0 + r) * QKVLD + c4);
        }
        #pragma unroll
        for (int u = 0; u < 4; u++) {
            int idx = tid + u * 256;
            int r = idx >> 4, c4 = (idx & 15) << 2;
            CP16(vb + (uint32_t)((r * FRS + c4) * 4), Vg + (size_t)r * SS_ + j0 + c4);
        }
        CP_COMMIT();
    };
    load_kv(0, 0);

    float ctxa[4][2][4] = {};
    float mrow[4][2], lrow[4][2];
    #pragma unroll
    for (int mt = 0; mt < 4; mt++) {
        mrow[mt][0] = -1e30f; mrow[mt][1] = -1e30f;
        lrow[mt][0] = 0.f;    lrow[mt][1] = 0.f;
    }

    const int IT = SS_ / 64;
    for (int j = 0; j < IT; j++) {
        const int s = j & 1;
        __syncthreads();
        if (j + 1 < IT) { load_kv(j + 1, s ^ 1); CP_WAIT1(); }
        else            { CP_WAIT0(); }
        __syncthreads();

        // ---- S = Q @ K^T ----
        float sacc[4][2][4] = {};
        const uint32_t sKs = sb + (uint32_t)((OFF_K + s * 64 * FRS) * 4);
        #pragma unroll
        for (int kk = 0; kk < 8; kk++) {
            uint32_t af[4][4];
            #pragma unroll
            for (int mt = 0; mt < 4; mt++) {
                int rr = wm * 64 + mt * 16 + ((seg & 1) << 3) + l8;
                int cc = kk * 8 + ((seg >> 1) << 2);
                LDSM4(af[mt][0], af[mt][1], af[mt][2], af[mt][3],
                      sQ + (uint32_t)((rr * FRS + cc) * 4));
            }
            uint32_t bf[2][2];
            {
                int nn = wn * 16 + ((seg >> 1) << 3) + l8;
                int cc = kk * 8 + ((seg & 1) << 2);
                LDSM4(bf[0][0], bf[0][1], bf[1][0], bf[1][1],
                      sKs + (uint32_t)((nn * FRS + cc) * 4));
            }
            #pragma unroll
            for (int nt = 0; nt < 2; nt++)
                #pragma unroll
                for (int mt = 0; mt < 4; mt++)
                    mma1688(sacc[mt][nt], af[mt], bf[nt][0], bf[nt][1]);
        }

        // ---- scale + mask, local row max ----
        const int j0 = j * 64;
        float lmax[4][2];
        #pragma unroll
        for (int mt = 0; mt < 4; mt++) { lmax[mt][0] = -1e30f; lmax[mt][1] = -1e30f; }
        #pragma unroll
        for (int nt = 0; nt < 2; nt++) {
            int cl = wn * 16 + nt * 8 + 2 * (lane & 3);
            float2 md = *reinterpret_cast<const float2*>(&Madd[j0 + cl]);
            #pragma unroll
            for (int mt = 0; mt < 4; mt++) {
                sacc[mt][nt][0] = sacc[mt][nt][0] * 0.125f + md.x;
                sacc[mt][nt][1] = sacc[mt][nt][1] * 0.125f + md.y;
                sacc[mt][nt][2] = sacc[mt][nt][2] * 0.125f + md.x;
                sacc[mt][nt][3] = sacc[mt][nt][3] * 0.125f + md.y;
                lmax[mt][0] = fmaxf(lmax[mt][0], fmaxf(sacc[mt][nt][0], sacc[mt][nt][1]));
                lmax[mt][1] = fmaxf(lmax[mt][1], fmaxf(sacc[mt][nt][2], sacc[mt][nt][3]));
            }
        }
        #pragma unroll
        for (int mt = 0; mt < 4; mt++)
            #pragma unroll
            for (int h2 = 0; h2 < 2; h2++) {
                float v = lmax[mt][h2];
                v = fmaxf(v, __shfl_xor_sync(0xffffffffu, v, 1));
                v = fmaxf(v, __shfl_xor_sync(0xffffffffu, v, 2));
                lmax[mt][h2] = v;
            }
        if ((lane & 3) == 0) {
            #pragma unroll
            for (int mt = 0; mt < 4; mt++)
                #pragma unroll
                for (int h2 = 0; h2 < 2; h2++) {
                    int row = wm * 64 + mt * 16 + h2 * 8 + (lane >> 2);
                    Pmax[wn * 128 + row] = lmax[mt][h2];
                }
        }
        __syncthreads();

        float alpha[4][2], lsum[4][2];
        #pragma unroll
        for (int mt = 0; mt < 4; mt++)
            #pragma unroll
            for (int h2 = 0; h2 < 2; h2++) {
                int row = wm * 64 + mt * 16 + h2 * 8 + (lane >> 2);
                float tm = fmaxf(fmaxf(Pmax[row], Pmax[128 + row]),
                                 fmaxf(Pmax[256 + row], Pmax[384 + row]));
                float mo = mrow[mt][h2];
                float mn = fmaxf(mo, tm);
                mrow[mt][h2]  = mn;
                alpha[mt][h2] = __expf(mo - mn);
                lsum[mt][h2]  = 0.f;
            }
        #pragma unroll
        for (int nt = 0; nt < 2; nt++) {
            int cl = wn * 16 + nt * 8 + 2 * (lane & 3);
            #pragma unroll
            for (int mt = 0; mt < 4; mt++)
                #pragma unroll
                for (int h2 = 0; h2 < 2; h2++) {
                    float p0 = __expf(sacc[mt][nt][2 * h2 + 0] - mrow[mt][h2]);
                    float p1 = __expf(sacc[mt][nt][2 * h2 + 1] - mrow[mt][h2]);
                    lsum[mt][h2] += p0 + p1;
                    int row = wm * 64 + mt * 16 + h2 * 8 + (lane >> 2);
                    float2 pp; pp.x = tf32r(p0); pp.y = tf32r(p1);
                    *reinterpret_cast<float2*>(&Ps[row * FRS + cl]) = pp;
                }
        }
        #pragma unroll
        for (int mt = 0; mt < 4; mt++)
            #pragma unroll
            for (int h2 = 0; h2 < 2; h2++) {
                float v = lsum[mt][h2];
                v += __shfl_xor_sync(0xffffffffu, v, 1);
                v += __shfl_xor_sync(0xffffffffu, v, 2);
                lsum[mt][h2] = v;
            }
        if ((lane & 3) == 0) {
            #pragma unroll
            for (int mt = 0; mt < 4; mt++)
                #pragma unroll
                for (int h2 = 0; h2 < 2; h2++) {
                    int row = wm * 64 + mt * 16 + h2 * 8 + (lane >> 2);
                    Psum[wn * 128 + row] = lsum[mt][h2];
                }
        }
        __syncthreads();
        #pragma unroll
        for (int mt = 0; mt < 4; mt++)
            #pragma unroll
            for (int h2 = 0; h2 < 2; h2++) {
                int row = wm * 64 + mt * 16 + h2 * 8 + (lane >> 2);
                float ts = Psum[row] + Psum[128 + row] + Psum[256 + row] + Psum[384 + row];
                lrow[mt][h2] = lrow[mt][h2] * alpha[mt][h2] + ts;
                #pragma unroll
                for (int nt = 0; nt < 2; nt++) {
                    ctxa[mt][nt][2 * h2 + 0] *= alpha[mt][h2];
                    ctxa[mt][nt][2 * h2 + 1] *= alpha[mt][h2];
                }
            }

        // ---- ctx += P @ V^T ----
        const uint32_t sVs = sb + (uint32_t)((OFF_V + s * 64 * FRS) * 4);
        #pragma unroll
        for (int kk = 0; kk < 8; kk++) {
            uint32_t af[4][4];
            #pragma unroll
            for (int mt = 0; mt < 4; mt++) {
                int rr = wm * 64 + mt * 16 + ((seg & 1) << 3) + l8;
                int cc = kk * 8 + ((seg >> 1) << 2);
                LDSM4(af[mt][0], af[mt][1], af[mt][2], af[mt][3],
                      sP + (uint32_t)((rr * FRS + cc) * 4));
            }
            uint32_t bf[2][2];
            {
                int nn = wn * 16 + ((seg >> 1) << 3) + l8;
                int cc = kk * 8 + ((seg & 1) << 2);
                LDSM4(bf[0][0], bf[0][1], bf[1][0], bf[1][1],
                      sVs + (uint32_t)((nn * FRS + cc) * 4));
            }
            #pragma unroll
            for (int nt = 0; nt < 2; nt++)
                #pragma unroll
                for (int mt = 0; mt < 4; mt++)
                    mma1688(ctxa[mt][nt], af[mt], bf[nt][0], bf[nt][1]);
        }
    }

    #pragma unroll
    for (int mt = 0; mt < 4; mt++)
        #pragma unroll
        for (int h2 = 0; h2 < 2; h2++) {
            int row = wm * 64 + mt * 16 + h2 * 8 + (lane >> 2);
            float inv = 1.0f / lrow[mt][h2];
            #pragma unroll
            for (int nt = 0; nt < 2; nt++) {
                int cl = wn * 16 + nt * 8 + 2 * (lane & 3);
                float2 o;
                o.x = tf32r(ctxa[mt][nt][2 * h2 + 0] * inv);
                o.y = tf32r(ctxa[mt][nt][2 * h2 + 1] * inv);
                *reinterpret_cast<float2*>(
                    ctx + ((size_t)bb * SS_ + q0 + row) * HID_ + hh * 64 + cl) = o;
            }
        }
}

// ---------------- tf32 mma.sync GEMM: 3-stage cp.async, 1 sync/iter ----------------
template<int EPI, bool RND>
__global__ __launch_bounds__(256, 2) void tc_gemm(
    int M, int N, int K,
    const float* __restrict__ A,  int lda,
    const float* __restrict__ Bm, int ldb,
    float* __restrict__ C,        int ldc,
    const float* __restrict__ bias, const float* __restrict__ residual,
    float scale)
{
    constexpr int RS  = 36;
    constexpr int ASZ = 128 * RS;
    constexpr int BSZ = 128 * RS;
    constexpr int STG = ASZ + BSZ;       // floats per stage
    constexpr int NT  = 4;               // warp n-tiles (warp tile 64x32)

    extern __shared__ __align__(16) float smem[];

    const int tid  = threadIdx.x;
    const int wid  = tid >> 5, lane = tid & 31;
    const int wm   = wid >> 2, wn = wid & 3;
    const int seg  = lane >> 3, l8 = lane & 7;
    const int row0 = blockIdx.y * 128;
    const int col0 = blockIdx.x * 128;

    const uint32_t sbase = smem_u32(smem);

    float acc[4][NT][4];
    #pragma unroll
    for (int i = 0; i < 4; i++)
        #pragma unroll
        for (int j = 0; j < NT; j++)
            #pragma unroll
            for (int e = 0; e < 4; e++) acc[i][j][e] = 0.0f;

    const int nk = K >> 5;

    auto load_stage = [&](int i, int s) {
        const int k0 = i << 5;
        uint32_t abase = sbase + (uint32_t)(s * STG) * 4u;
        uint32_t bbase = abase + (uint32_t)ASZ * 4u;
        #pragma unroll
        for (int u = 0; u < 4; u++) {
            int idx = tid + u * 256;
            int r = idx >> 3, c4 = (idx & 7) << 2;
            CP16(abase + (uint32_t)(r * RS + c4) * 4u,
                 A + (size_t)(row0 + r) * lda + k0 + c4);
        }
        #pragma unroll
        for (int u = 0; u < 4; u++) {
            int idx = tid + u * 256;
            int r = idx >> 3, c4 = (idx & 7) << 2;
            CP16(bbase + (uint32_t)(r * RS + c4) * 4u,
                 Bm + (size_t)(col0 + r) * ldb + k0 + c4);
        }
        CP_COMMIT();
    };

    load_stage(0, 0);
    load_stage(1, 1);

    int s = 0;
    for (int i = 0; i < nk; i++) {
        if (i == nk - 1) { CP_WAIT0(); } else { CP_WAIT1(); }
        __syncthreads();
        int ns = s + 2; if (ns >= 3) ns -= 3;
        if (i + 2 < nk) load_stage(i + 2, ns);

        const uint32_t sAs = sbase + (uint32_t)(s * STG) * 4u;
        const uint32_t sBs = sAs + (uint32_t)ASZ * 4u;

        #pragma unroll
        for (int kk = 0; kk < 4; kk++) {
            uint32_t af[4][4];
            #pragma unroll
            for (int mt = 0; mt < 4; mt++) {
                int rr = wm * 64 + mt * 16 + ((seg & 1) << 3) + l8;
                int cc = kk * 8 + ((seg >> 1) << 2);
                LDSM4(af[mt][0], af[mt][1], af[mt][2], af[mt][3],
                      sAs + (uint32_t)((rr * RS + cc) * 4));
            }
            uint32_t bf[NT][2];
            #pragma unroll
            for (int ntp = 0; ntp < NT / 2; ntp++) {
                int nn = wn * 32 + ntp * 16 + ((seg >> 1) << 3) + l8;
                int cc = kk * 8 + ((seg & 1) << 2);
                LDSM4(bf[2*ntp][0], bf[2*ntp][1], bf[2*ntp+1][0], bf[2*ntp+1][1],
                      sBs + (uint32_t)((nn * RS + cc) * 4));
            }
            #pragma unroll
            for (int nt = 0; nt < NT; nt++)
                #pragma unroll
                for (int mt = 0; mt < 4; mt++)
                    mma1688(acc[mt][nt], af[mt], bf[nt][0], bf[nt][1]);
        }
        s++; if (s == 3) s = 0;
    }

    #pragma unroll
    for (int mt = 0; mt < 4; mt++) {
        #pragma unroll
        for (int nt = 0; nt < NT; nt++) {
            int r0 = row0 + wm * 64 + mt * 16 + (lane >> 2);
            int c0 = col0 + wn * 32 + nt * 8 + 2 * (lane & 3);
            #pragma unroll
            for (int half = 0; half < 2; half++) {
                int r = r0 + half * 8;
                float v0 = acc[mt][nt][2 * half + 0];
                float v1 = acc[mt][nt][2 * half + 1];
                if (bias) {
                    v0 += __ldg(&bias[c0]);
                    v1 += __ldg(&bias[c0 + 1]);
                }
                if (EPI == 2) {
                    v0 = 0.5f * v0 * (1.0f + erff(v0 * 0.70710678118654752f));
                    v1 = 0.5f * v1 * (1.0f + erff(v1 * 0.70710678118654752f));
                }
                if (EPI == 3) {
                    float2 rr = *reinterpret_cast<const float2*>(
                        residual + (size_t)r * ldc + c0);
                    v0 += rr.x; v1 += rr.y;
                }
                if (RND) { v0 = tf32r(v0); v1 = tf32r(v1); }
                float2 o; o.x = v0; o.y = v1;
                *reinterpret_cast<float2*>(C + (size_t)r * ldc + c0) = o;
            }
        }
    }
}

// ---------------- launch ----------------
extern "C" void kernel_launch(void* const* d_in, const int* in_sizes, int n_in,
                              void* d_out, int out_size) {
    const float* x   = (const float*)d_in[0];
    const float* am  = (const float*)d_in[1];
    const float* Wq  = (const float*)d_in[2];
    const float* bq  = (const float*)d_in[3];
    const float* Wk  = (const float*)d_in[4];
    const float* bk  = (const float*)d_in[5];
    const float* Wv  = (const float*)d_in[6];
    const float* bv  = (const float*)d_in[7];
    const float* Wo  = (const float*)d_in[8];
    const float* bo  = (const float*)d_in[9];
    const float* W1  = (const float*)d_in[10];
    const float* b1  = (const float*)d_in[11];
    const float* W2  = (const float*)d_in[12];
    const float* b2  = (const float*)d_in[13];
    const float* g1  = (const float*)d_in[14];
    const float* be1 = (const float*)d_in[15];
    const float* g2  = (const float*)d_in[16];
    const float* be2 = (const float*)d_in[17];
    float* out = (float*)d_out;

    float *h, *qkv, *vt, *ctx, *x2, *h2, *ff, *wr, *bqkv;
    cudaGetSymbolAddress((void**)&h,    g_h);
    cudaGetSymbolAddress((void**)&qkv,  g_qkv);
    cudaGetSymbolAddress((void**)&vt,   g_vt);
    cudaGetSymbolAddress((void**)&ctx,  g_ctx);
    cudaGetSymbolAddress((void**)&x2,   g_x2);
    cudaGetSymbolAddress((void**)&h2,   g_h2);
    cudaGetSymbolAddress((void**)&ff,   g_ff);
    cudaGetSymbolAddress((void**)&wr,   g_wr);
    cudaGetSymbolAddress((void**)&bqkv, g_bqkv);

    float* rWqkv = wr;                       // q|k|v contiguous = [3072, 1024]
    float* rWo = wr + 3 * 1024 * 1024;
    float* rW1 = wr + 4 * 1024 * 1024;
    float* rW2 = wr + 8 * 1024 * 1024;

    const int SM3 = 3 * (128 * 36 + 128 * 36) * 4;   // 110592
    cudaFuncSetAttribute(tc_gemm<0,true >, cudaFuncAttributeMaxDynamicSharedMemorySize, SM3);
    cudaFuncSetAttribute(tc_gemm<2,true >, cudaFuncAttributeMaxDynamicSharedMemorySize, SM3);
    cudaFuncSetAttribute(tc_gemm<3,false>, cudaFuncAttributeMaxDynamicSharedMemorySize, SM3);
    cudaFuncSetAttribute(flash_kernel, cudaFuncAttributeMaxDynamicSharedMemorySize, FL_SMEM);

    dim3 blk(256);

    // 0: pack qkv bias
    pack_bias_kernel<<<12, blk>>>(bq, bk, bv, bqkv);
    // 1: round Wq|Wk|Wv|Wo
    round4_kernel<<<4096, blk>>>(Wq, Wk, Wv, Wo, rWqkv, rWqkv + 1024*1024,
                                 rWqkv + 2*1024*1024, rWo);
    // 2: h = LN1(x)
    ln_kernel<<<TOK_, blk>>>(x, g1, be1, h);
    // 3: qkv = h @ [Wq|Wk|Wv]^T + b   (one GEMM, N=3072)
    tc_gemm<0,true><<<dim3(QKVLD/128, TOK_/128), blk, SM3>>>(TOK_, QKVLD, HID_,
        h, HID_,  rWqkv, HID_,  qkv, QKVLD,  bqkv, nullptr, 0.f);
    // 4: vt = transpose(v)
    transpose_v_kernel<<<dim3(SS_/32, BB_*NH_*2), blk>>>(qkv, vt);
    // 5: fused attention -> ctx
    flash_kernel<<<dim3(SS_/128, BB_*NH_), blk, FL_SMEM>>>(qkv, vt, am, ctx);
    // 6: round W1|W2
    round2_kernel<<<8192, blk>>>(W1, W2, rW1, rW2);
    // 7: x2 = x + ctx @ Wo^T + bo
    tc_gemm<3,false><<<dim3(HID_/128, TOK_/128), blk, SM3>>>(TOK_, HID_, HID_,
        ctx, HID_,  rWo, HID_,  x2, HID_,  bo, x, 0.f);
    // 8: h2 = LN2(x2)
    ln_kernel<<<TOK_, blk>>>(x2, g2, be2, h2);
    // 9: ff = gelu(h2 @ W1^T + b1)
    tc_gemm<2,true><<<dim3(FF_/128, TOK_/128), blk, SM3>>>(TOK_, FF_, HID_,
        h2, HID_,  rW1, HID_,  ff, FF_,  b1, nullptr, 0.f);
    // 10: out = x2 + ff @ W2^T + b2
    tc_gemm<3,false><<<dim3(HID_/128, TOK_/128), blk, SM3>>>(TOK_, HID_, FF_,
        ff, FF_,  rW2, FF_,  out, HID_,  b2, x2, 0.f);
}

// round 8
// speedup vs baseline: 6.4335x; 1.6896x over previous
#include <cuda_runtime.h>
#include <cuda_bf16.h>
#include <math.h>
#include <stdint.h>

#define BB_   2
#define SS_   2048
#define HID_  1024
#define NH_   16
#define HD_   64
#define FF_   4096
#define TOK_  (BB_*SS_)   // 4096
#define QKVLD 3072

// ---------------- scratch ----------------
__device__ __nv_bfloat16 g_h  [TOK_*HID_];
__device__ __nv_bfloat16 g_qkv[TOK_*3*HID_];       // [TOK, 3072] = q|k|v
__device__ __nv_bfloat16 g_vt [TOK_*HID_];         // [B*H, 64, S]
__device__ __nv_bfloat16 g_ctx[TOK_*HID_];
__device__ float         g_x2 [TOK_*HID_];
__device__ __nv_bfloat16 g_h2 [TOK_*HID_];
__device__ __nv_bfloat16 g_ff [TOK_*FF_];
__device__ __nv_bfloat16 g_wb [12*1024*1024];      // bf16 weights (q|k|v|o|W1|W2)
__device__ float         g_bqkv[3*HID_];

// ---------------- helpers ----------------
__device__ __forceinline__ uint32_t bf2(float x, float y) {
    __nv_bfloat162 t = __floats2bfloat162_rn(x, y);
    return *reinterpret_cast<uint32_t*>(&t);
}
__device__ __forceinline__ uint32_t smem_u32(const void* p) {
    uint32_t a;
    asm("{ .reg .u64 t; cvta.to.shared.u64 t, %1; cvt.u32.u64 %0, t; }" : "=r"(a) : "l"(p));
    return a;
}
#define CP16(dst, src) \
    asm volatile("cp.async.cg.shared.global [%0], [%1], 16;" :: "r"(dst), "l"(src) : "memory")
#define CP_COMMIT() asm volatile("cp.async.commit_group;" ::: "memory")
#define CP_WAIT1()  asm volatile("cp.async.wait_group 1;" ::: "memory")
#define CP_WAIT0()  asm volatile("cp.async.wait_group 0;" ::: "memory")

#define LDSM4(R0, R1, R2, R3, ADDR) \
    asm volatile("ldmatrix.sync.aligned.m8n8.x4.shared.b16 {%0,%1,%2,%3}, [%4];" \
        : "=r"(R0), "=r"(R1), "=r"(R2), "=r"(R3) : "r"(ADDR))

__device__ __forceinline__ void mma16816(float* c, const uint32_t* a, uint32_t b0, uint32_t b1) {
    asm volatile(
        "mma.sync.aligned.m16n8k16.row.col.f32.bf16.bf16.f32 "
        "{%0,%1,%2,%3}, {%4,%5,%6,%7}, {%8,%9}, {%0,%1,%2,%3};"
        : "+f"(c[0]), "+f"(c[1]), "+f"(c[2]), "+f"(c[3])
        : "r"(a[0]), "r"(a[1]), "r"(a[2]), "r"(a[3]), "r"(b0), "r"(b1));
}

// ---------------- bias pack ----------------
__global__ void pack_bias_kernel(const float* __restrict__ a, const float* __restrict__ b,
                                 const float* __restrict__ c, float* __restrict__ o) {
    int i = blockIdx.x * blockDim.x + threadIdx.x;
    if (i < HID_)            o[i] = a[i];
    else if (i < 2 * HID_)   o[i] = b[i - HID_];
    else if (i < 3 * HID_)   o[i] = c[i - 2 * HID_];
}

// ---------------- weight conversion fp32 -> bf16 ----------------
__global__ void round4_kernel(const float* __restrict__ a, const float* __restrict__ b,
                              const float* __restrict__ c, const float* __restrict__ d,
                              __nv_bfloat16* __restrict__ oa, __nv_bfloat16* __restrict__ ob,
                              __nv_bfloat16* __restrict__ oc, __nv_bfloat16* __restrict__ od) {
    int i = blockIdx.x * blockDim.x + threadIdx.x;   // float4 index over 4x1M
    int seg = i >> 18, off = i & 262143;
    const float4* sp; __nv_bfloat16* dp;
    if      (seg == 0) { sp = (const float4*)a; dp = oa; }
    else if (seg == 1) { sp = (const float4*)b; dp = ob; }
    else if (seg == 2) { sp = (const float4*)c; dp = oc; }
    else               { sp = (const float4*)d; dp = od; }
    float4 v = sp[off];
    reinterpret_cast<uint2*>(dp)[off] = make_uint2(bf2(v.x, v.y), bf2(v.z, v.w));
}
__global__ void round2_kernel(const float* __restrict__ a, const float* __restrict__ b,
                              __nv_bfloat16* __restrict__ oa, __nv_bfloat16* __restrict__ ob) {
    int i = blockIdx.x * blockDim.x + threadIdx.x;   // float4 index over 2x4M
    int seg = i >> 20, off = i & 1048575;
    const float4* sp = seg ? (const float4*)b : (const float4*)a;
    __nv_bfloat16* dp = seg ? ob : oa;
    float4 v = sp[off];
    reinterpret_cast<uint2*>(dp)[off] = make_uint2(bf2(v.x, v.y), bf2(v.z, v.w));
}

// ---------------- block reduction ----------------
template<bool MAX>
__device__ __forceinline__ float block_reduce_256(float v) {
    __shared__ float sh[8];
    int lane = threadIdx.x & 31, w = threadIdx.x >> 5;
    #pragma unroll
    for (int o = 16; o; o >>= 1) {
        float u = __shfl_xor_sync(0xffffffffu, v, o);
        v = MAX ? fmaxf(v, u) : v + u;
    }
    if (lane == 0) sh[w] = v;
    __syncthreads();
    if (w == 0) {
        v = sh[lane & 7];
        #pragma unroll
        for (int o = 4; o; o >>= 1) {
            float u = __shfl_xor_sync(0xffffffffu, v, o);
            v = MAX ? fmaxf(v, u) : v + u;
        }
        if (lane == 0) sh[0] = v;
    }
    __syncthreads();
    float r = sh[0];
    __syncthreads();
    return r;
}

// ---------------- LayerNorm (fp32 in -> bf16 out) ----------------
__global__ void ln_kernel(const float* __restrict__ x, const float* __restrict__ g,
                          const float* __restrict__ beta, __nv_bfloat16* __restrict__ out) {
    size_t base = (size_t)blockIdx.x * HID_;
    const float4* xp = reinterpret_cast<const float4*>(x + base);
    int t = threadIdx.x;
    float4 v = xp[t];
    float s = v.x + v.y + v.z + v.w;
    s = block_reduce_256<false>(s);
    float mean = s * (1.0f / HID_);
    float dx = v.x - mean, dy = v.y - mean, dz = v.z - mean, dw = v.w - mean;
    float q = dx*dx + dy*dy + dz*dz + dw*dw;
    q = block_reduce_256<false>(q);
    float r = rsqrtf(q * (1.0f / HID_) + 1e-5f);
    float4 gv = reinterpret_cast<const float4*>(g)[t];
    float4 bv = reinterpret_cast<const float4*>(beta)[t];
    uint2 o;
    o.x = bf2(dx * r * gv.x + bv.x, dy * r * gv.y + bv.y);
    o.y = bf2(dz * r * gv.z + bv.z, dw * r * gv.w + bv.w);
    reinterpret_cast<uint2*>(out + base)[t] = o;
}

// ---------------- transpose V (bf16 -> bf16, bit-exact copy) ----------------
__global__ void transpose_v_kernel(const __nv_bfloat16* __restrict__ qkv,
                                   __nv_bfloat16* __restrict__ vt) {
    __shared__ __nv_bfloat16 t[32][34];
    int bz = blockIdx.y;
    int b = bz / (NH_ * 2);
    int rem = bz % (NH_ * 2);
    int h = rem >> 1;
    int d0 = (rem & 1) * 32;
    int s0 = blockIdx.x * 32;
    int tx = threadIdx.x & 31, ty = threadIdx.x >> 5;
    #pragma unroll
    for (int i = 0; i < 32; i += 8)
        t[ty + i][tx] = qkv[((size_t)b * SS_ + s0 + ty + i) * QKVLD + 2 * HID_ + h * 64 + d0 + tx];
    __syncthreads();
    #pragma unroll
    for (int i = 0; i < 32; i += 8)
        vt[(((size_t)b * NH_ + h) * 64 + d0 + ty + i) * SS_ + s0 + tx] = t[tx][ty + i];
}

// ---------------- fused flash attention (bf16 operands, fp32 softmax) ----------------
// smem (bf16 units): Q 128x72 | K 2x64x72 | V 2x64x72 | P 128x72 ; then fp32 Madd/Pmax/Psum
#define FFS 72
#define FQ  0
#define FK  (128*FFS)
#define FV  (FK + 2*64*FFS)
#define FP  (FV + 2*64*FFS)
#define FL_FLT ((FP + 128*FFS) * 2)        // byte offset of float region
#define FL_SMEM (FL_FLT + (2048 + 512 + 512) * 4)

__global__ __launch_bounds__(256, 1) void flash_kernel(
    const __nv_bfloat16* __restrict__ qkv, const __nv_bfloat16* __restrict__ vt,
    const float* __restrict__ am, __nv_bfloat16* __restrict__ ctx)
{
    extern __shared__ __align__(16) char smc[];
    float* Madd = reinterpret_cast<float*>(smc + FL_FLT);
    float* Pmax = Madd + 2048;
    float* Psum = Pmax + 512;

    const int tid = threadIdx.x, lane = tid & 31, wid = tid >> 5;
    const int wm = wid >> 2, wn = wid & 3;
    const int qq = lane >> 3, l8 = lane & 7;
    const int arow = ((qq & 1) << 3) + l8, acol = (qq >> 1) << 3;   // A ldmatrix pattern
    const int brow = ((qq >> 1) << 3) + l8, bcol = (qq & 1) << 3;   // B ldmatrix pattern
    const int qt = blockIdx.x, bh = blockIdx.y;
    const int bb = bh >> 4, hh = bh & 15;
    const int q0 = qt * 128;

    const __nv_bfloat16* Qg = qkv + ((size_t)bb * SS_ + q0) * QKVLD + hh * 64;
    const __nv_bfloat16* Kg = qkv + (size_t)bb * SS_ * QKVLD + HID_ + hh * 64;
    const __nv_bfloat16* Vg = vt + (size_t)bh * 64 * SS_;

    const uint32_t sb = smem_u32(smc);
    const uint32_t sQ = sb + FQ * 2, sP = sb + FP * 2;
    __nv_bfloat16* Ps = reinterpret_cast<__nv_bfloat16*>(smc) + FP;

    // Q tile 128x64 bf16: 1024 16B chunks, 4/thread
    #pragma unroll
    for (int u = 0; u < 4; u++) {
        int idx = tid + u * 256;
        int r = idx >> 3, c8 = (idx & 7) << 3;
        CP16(sQ + (uint32_t)((r * FFS + c8) * 2), Qg + (size_t)r * QKVLD + c8);
    }
    CP_COMMIT();
    #pragma unroll
    for (int u = 0; u < 8; u++) {
        int i = tid + u * 256;
        Madd[i] = (__ldg(&am[(size_t)bb * SS_ + i]) - 1.0f) * 10000.0f;
    }

    auto load_kv = [&](int j, int s) {
        const int j0 = j * 64;
        uint32_t kb = sb + (uint32_t)((FK + s * 64 * FFS) * 2);
        uint32_t vb = sb + (uint32_t)((FV + s * 64 * FFS) * 2);
        #pragma unroll
        for (int u = 0; u < 2; u++) {
            int idx = tid + u * 256;
            int r = idx >> 3, c8 = (idx & 7) << 3;
            CP16(kb + (uint32_t)((r * FFS + c8) * 2), Kg + (size_t)(j0 + r) * QKVLD + c8);
        }
        #pragma unroll
        for (int u = 0; u < 2; u++) {
            int idx = tid + u * 256;
            int r = idx >> 3, c8 = (idx & 7) << 3;
            CP16(vb + (uint32_t)((r * FFS + c8) * 2), Vg + (size_t)r * SS_ + j0 + c8);
        }
        CP_COMMIT();
    };
    load_kv(0, 0);

    float ctxa[4][2][4] = {};
    float mrow[4][2], lrow[4][2];
    #pragma unroll
    for (int mt = 0; mt < 4; mt++) {
        mrow[mt][0] = -1e30f; mrow[mt][1] = -1e30f;
        lrow[mt][0] = 0.f;    lrow[mt][1] = 0.f;
    }

    const int IT = SS_ / 64;
    for (int j = 0; j < IT; j++) {
        const int s = j & 1;
        __syncthreads();
        if (j + 1 < IT) { load_kv(j + 1, s ^ 1); CP_WAIT1(); }
        else            { CP_WAIT0(); }
        __syncthreads();

        // ---- S = Q @ K^T (K dim = dh = 64 -> 4 k16 steps) ----
        float sacc[4][2][4] = {};
        const uint32_t sKs = sb + (uint32_t)((FK + s * 64 * FFS) * 2);
        #pragma unroll
        for (int kk = 0; kk < 4; kk++) {
            uint32_t af[4][4];
            #pragma unroll
            for (int mt = 0; mt < 4; mt++) {
                int rr = wm * 64 + mt * 16 + arow;
                LDSM4(af[mt][0], af[mt][1], af[mt][2], af[mt][3],
                      sQ + (uint32_t)((rr * FFS + kk * 16 + acol) * 2));
            }
            uint32_t b4[4];
            {
                int nn = wn * 16 + brow;
                LDSM4(b4[0], b4[1], b4[2], b4[3],
                      sKs + (uint32_t)((nn * FFS + kk * 16 + bcol) * 2));
            }
            #pragma unroll
            for (int mt = 0; mt < 4; mt++) {
                mma16816(sacc[mt][0], af[mt], b4[0], b4[1]);
                mma16816(sacc[mt][1], af[mt], b4[2], b4[3]);
            }
        }

        // ---- scale + mask, local row max ----
        const int j0 = j * 64;
        float lmax[4][2];
        #pragma unroll
        for (int mt = 0; mt < 4; mt++) { lmax[mt][0] = -1e30f; lmax[mt][1] = -1e30f; }
        #pragma unroll
        for (int nt = 0; nt < 2; nt++) {
            int cl = wn * 16 + nt * 8 + 2 * (lane & 3);
            float2 md = *reinterpret_cast<const float2*>(&Madd[j0 + cl]);
            #pragma unroll
            for (int mt = 0; mt < 4; mt++) {
                sacc[mt][nt][0] = sacc[mt][nt][0] * 0.125f + md.x;
                sacc[mt][nt][1] = sacc[mt][nt][1] * 0.125f + md.y;
                sacc[mt][nt][2] = sacc[mt][nt][2] * 0.125f + md.x;
                sacc[mt][nt][3] = sacc[mt][nt][3] * 0.125f + md.y;
                lmax[mt][0] = fmaxf(lmax[mt][0], fmaxf(sacc[mt][nt][0], sacc[mt][nt][1]));
                lmax[mt][1] = fmaxf(lmax[mt][1], fmaxf(sacc[mt][nt][2], sacc[mt][nt][3]));
            }
        }
        #pragma unroll
        for (int mt = 0; mt < 4; mt++)
            #pragma unroll
            for (int h2 = 0; h2 < 2; h2++) {
                float v = lmax[mt][h2];
                v = fmaxf(v, __shfl_xor_sync(0xffffffffu, v, 1));
                v = fmaxf(v, __shfl_xor_sync(0xffffffffu, v, 2));
                lmax[mt][h2] = v;
            }
        if ((lane & 3) == 0) {
            #pragma unroll
            for (int mt = 0; mt < 4; mt++)
                #pragma unroll
                for (int h2 = 0; h2 < 2; h2++) {
                    int row = wm * 64 + mt * 16 + h2 * 8 + (lane >> 2);
                    Pmax[wn * 128 + row] = lmax[mt][h2];
                }
        }
        __syncthreads();

        float alpha[4][2], lsum[4][2];
        #pragma unroll
        for (int mt = 0; mt < 4; mt++)
            #pragma unroll
            for (int h2 = 0; h2 < 2; h2++) {
                int row = wm * 64 + mt * 16 + h2 * 8 + (lane >> 2);
                float tm = fmaxf(fmaxf(Pmax[row], Pmax[128 + row]),
                                 fmaxf(Pmax[256 + row], Pmax[384 + row]));
                float mo = mrow[mt][h2];
                float mn = fmaxf(mo, tm);
                mrow[mt][h2]  = mn;
                alpha[mt][h2] = __expf(mo - mn);
                lsum[mt][h2]  = 0.f;
            }
        #pragma unroll
        for (int nt = 0; nt < 2; nt++) {
            int cl = wn * 16 + nt * 8 + 2 * (lane & 3);
            #pragma unroll
            for (int mt = 0; mt < 4; mt++)
                #pragma unroll
                for (int h2 = 0; h2 < 2; h2++) {
                    float p0 = __expf(sacc[mt][nt][2 * h2 + 0] - mrow[mt][h2]);
                    float p1 = __expf(sacc[mt][nt][2 * h2 + 1] - mrow[mt][h2]);
                    lsum[mt][h2] += p0 + p1;
                    int row = wm * 64 + mt * 16 + h2 * 8 + (lane >> 2);
                    *reinterpret_cast<uint32_t*>(&Ps[row * FFS + cl]) = bf2(p0, p1);
                }
        }
        #pragma unroll
        for (int mt = 0; mt < 4; mt++)
            #pragma unroll
            for (int h2 = 0; h2 < 2; h2++) {
                float v = lsum[mt][h2];
                v += __shfl_xor_sync(0xffffffffu, v, 1);
                v += __shfl_xor_sync(0xffffffffu, v, 2);
                lsum[mt][h2] = v;
            }
        if ((lane & 3) == 0) {
            #pragma unroll
            for (int mt = 0; mt < 4; mt++)
                #pragma unroll
                for (int h2 = 0; h2 < 2; h2++) {
                    int row = wm * 64 + mt * 16 + h2 * 8 + (lane >> 2);
                    Psum[wn * 128 + row] = lsum[mt][h2];
                }
        }
        __syncthreads();
        #pragma unroll
        for (int mt = 0; mt < 4; mt++)
            #pragma unroll
            for (int h2 = 0; h2 < 2; h2++) {
                int row = wm * 64 + mt * 16 + h2 * 8 + (lane >> 2);
                float ts = Psum[row] + Psum[128 + row] + Psum[256 + row] + Psum[384 + row];
                lrow[mt][h2] = lrow[mt][h2] * alpha[mt][h2] + ts;
                #pragma unroll
                for (int nt = 0; nt < 2; nt++) {
                    ctxa[mt][nt][2 * h2 + 0] *= alpha[mt][h2];
                    ctxa[mt][nt][2 * h2 + 1] *= alpha[mt][h2];
                }
            }

        // ---- ctx += P @ V^T (K dim = 64 keys -> 4 k16 steps) ----
        const uint32_t sVs = sb + (uint32_t)((FV + s * 64 * FFS) * 2);
        #pragma unroll
        for (int kk = 0; kk < 4; kk++) {
            uint32_t af[4][4];
            #pragma unroll
            for (int mt = 0; mt < 4; mt++) {
                int rr = wm * 64 + mt * 16 + arow;
                LDSM4(af[mt][0], af[mt][1], af[mt][2], af[mt][3],
                      sP + (uint32_t)((rr * FFS + kk * 16 + acol) * 2));
            }
            uint32_t b4[4];
            {
                int nn = wn * 16 + brow;
                LDSM4(b4[0], b4[1], b4[2], b4[3],
                      sVs + (uint32_t)((nn * FFS + kk * 16 + bcol) * 2));
            }
            #pragma unroll
            for (int mt = 0; mt < 4; mt++) {
                mma16816(ctxa[mt][0], af[mt], b4[0], b4[1]);
                mma16816(ctxa[mt][1], af[mt], b4[2], b4[3]);
            }
        }
    }

    // ---- finalize: ctx / l -> bf16 ----
    #pragma unroll
    for (int mt = 0; mt < 4; mt++)
        #pragma unroll
        for (int h2 = 0; h2 < 2; h2++) {
            int row = wm * 64 + mt * 16 + h2 * 8 + (lane >> 2);
            float inv = 1.0f / lrow[mt][h2];
            #pragma unroll
            for (int nt = 0; nt < 2; nt++) {
                int cl = wn * 16 + nt * 8 + 2 * (lane & 3);
                *reinterpret_cast<uint32_t*>(
                    ctx + ((size_t)bb * SS_ + q0 + row) * HID_ + hh * 64 + cl) =
                    bf2(ctxa[mt][nt][2 * h2 + 0] * inv, ctxa[mt][nt][2 * h2 + 1] * inv);
            }
        }
}

// ---------------- bf16 mma GEMM: 128x128x64 chunks, 3-stage cp.async ----------------
// EPI: 0 = +bias -> bf16 out; 2 = gelu(+bias) -> bf16 out; 3 = +bias+residual -> fp32 out
template<int EPI>
__global__ __launch_bounds__(256, 2) void tc_gemm(
    int M, int N, int K,
    const __nv_bfloat16* __restrict__ A,  int lda,
    const __nv_bfloat16* __restrict__ Bm, int ldb,
    float* __restrict__ Cf, __nv_bfloat16* __restrict__ Cb, int ldc,
    const float* __restrict__ bias, const float* __restrict__ residual)
{
    constexpr int RS  = 72;              // bf16 stride (64 data + 8 pad)
    constexpr int ASZ = 128 * RS;        // bf16 elems per tile
    constexpr int STG = 2 * ASZ;
    constexpr int NT  = 4;

    extern __shared__ __align__(16) char smc[];

    const int tid  = threadIdx.x;
    const int wid  = tid >> 5, lane = tid & 31;
    const int wm   = wid >> 2, wn = wid & 3;
    const int qq   = lane >> 3, l8 = lane & 7;
    const int arow = ((qq & 1) << 3) + l8, acol = (qq >> 1) << 3;
    const int brow = ((qq >> 1) << 3) + l8, bcol = (qq & 1) << 3;
    const int row0 = blockIdx.y * 128;
    const int col0 = blockIdx.x * 128;

    const uint32_t sbase = smem_u32(smc);

    float acc[4][NT][4];
    #pragma unroll
    for (int i = 0; i < 4; i++)
        #pragma unroll
        for (int j = 0; j < NT; j++)
            #pragma unroll
            for (int e = 0; e < 4; e++) acc[i][j][e] = 0.0f;

    const int nk = K >> 6;

    auto load_stage = [&](int i, int s) {
        const int k0 = i << 6;
        uint32_t abase = sbase + (uint32_t)(s * STG) * 2u;
        uint32_t bbase = abase + (uint32_t)ASZ * 2u;
        #pragma unroll
        for (int u = 0; u < 4; u++) {
            int idx = tid + u * 256;
            int r = idx >> 3, c8 = (idx & 7) << 3;
            CP16(abase + (uint32_t)(r * RS + c8) * 2u,
                 A + (size_t)(row0 + r) * lda + k0 + c8);
        }
        #pragma unroll
        for (int u = 0; u < 4; u++) {
            int idx = tid + u * 256;
            int r = idx >> 3, c8 = (idx & 7) << 3;
            CP16(bbase + (uint32_t)(r * RS + c8) * 2u,
                 Bm + (size_t)(col0 + r) * ldb + k0 + c8);
        }
        CP_COMMIT();
    };

    load_stage(0, 0);
    load_stage(1, 1);

    int s = 0;
    for (int i = 0; i < nk; i++) {
        if (i == nk - 1) { CP_WAIT0(); } else { CP_WAIT1(); }
        __syncthreads();
        int ns = s + 2; if (ns >= 3) ns -= 3;
        if (i + 2 < nk) load_stage(i + 2, ns);

        const uint32_t sAs = sbase + (uint32_t)(s * STG) * 2u;
        const uint32_t sBs = sAs + (uint32_t)ASZ * 2u;

        #pragma unroll
        for (int kk = 0; kk < 4; kk++) {
            uint32_t af[4][4];
            #pragma unroll
            for (int mt = 0; mt < 4; mt++) {
                int rr = wm * 64 + mt * 16 + arow;
                LDSM4(af[mt][0], af[mt][1], af[mt][2], af[mt][3],
                      sAs + (uint32_t)((rr * RS + kk * 16 + acol) * 2));
            }
            uint32_t bf[NT][2];
            #pragma unroll
            for (int ntp = 0; ntp < NT / 2; ntp++) {
                int nn = wn * 32 + ntp * 16 + brow;
                LDSM4(bf[2*ntp][0], bf[2*ntp][1], bf[2*ntp+1][0], bf[2*ntp+1][1],
                      sBs + (uint32_t)((nn * RS + kk * 16 + bcol) * 2));
            }
            #pragma unroll
            for (int nt = 0; nt < NT; nt++)
                #pragma unroll
                for (int mt = 0; mt < 4; mt++)
                    mma16816(acc[mt][nt], af[mt], bf[nt][0], bf[nt][1]);
        }
        s++; if (s == 3) s = 0;
    }

    #pragma unroll
    for (int mt = 0; mt < 4; mt++) {
        #pragma unroll
        for (int nt = 0; nt < NT; nt++) {
            int r0 = row0 + wm * 64 + mt * 16 + (lane >> 2);
            int c0 = col0 + wn * 32 + nt * 8 + 2 * (lane & 3);
            #pragma unroll
            for (int half = 0; half < 2; half++) {
                int r = r0 + half * 8;
                float v0 = acc[mt][nt][2 * half + 0];
                float v1 = acc[mt][nt][2 * half + 1];
                v0 += __ldg(&bias[c0]);
                v1 += __ldg(&bias[c0 + 1]);
                if (EPI == 2) {
                    v0 = 0.5f * v0 * (1.0f + erff(v0 * 0.70710678118654752f));
                    v1 = 0.5f * v1 * (1.0f + erff(v1 * 0.70710678118654752f));
                }
                if (EPI == 3) {
                    float2 rr = *reinterpret_cast<const float2*>(
                        residual + (size_t)r * ldc + c0);
                    v0 += rr.x; v1 += rr.y;
                    float2 o; o.x = v0; o.y = v1;
                    *reinterpret_cast<float2*>(Cf + (size_t)r * ldc + c0) = o;
                } else {
                    *reinterpret_cast<uint32_t*>(Cb + (size_t)r * ldc + c0) = bf2(v0, v1);
                }
            }
        }
    }
}

// ---------------- launch ----------------
extern "C" void kernel_launch(void* const* d_in, const int* in_sizes, int n_in,
                              void* d_out, int out_size) {
    const float* x   = (const float*)d_in[0];
    const float* am  = (const float*)d_in[1];
    const float* Wq  = (const float*)d_in[2];
    const float* bq  = (const float*)d_in[3];
    const float* Wk  = (const float*)d_in[4];
    const float* bk  = (const float*)d_in[5];
    const float* Wv  = (const float*)d_in[6];
    const float* bv  = (const float*)d_in[7];
    const float* Wo  = (const float*)d_in[8];
    const float* bo  = (const float*)d_in[9];
    const float* W1  = (const float*)d_in[10];
    const float* b1  = (const float*)d_in[11];
    const float* W2  = (const float*)d_in[12];
    const float* b2  = (const float*)d_in[13];
    const float* g1  = (const float*)d_in[14];
    const float* be1 = (const float*)d_in[15];
    const float* g2  = (const float*)d_in[16];
    const float* be2 = (const float*)d_in[17];
    float* out = (float*)d_out;

    __nv_bfloat16 *h, *qkv, *vt, *ctx, *h2, *ff, *wb;
    float *x2, *bqkv;
    cudaGetSymbolAddress((void**)&h,    g_h);
    cudaGetSymbolAddress((void**)&qkv,  g_qkv);
    cudaGetSymbolAddress((void**)&vt,   g_vt);
    cudaGetSymbolAddress((void**)&ctx,  g_ctx);
    cudaGetSymbolAddress((void**)&x2,   g_x2);
    cudaGetSymbolAddress((void**)&h2,   g_h2);
    cudaGetSymbolAddress((void**)&ff,   g_ff);
    cudaGetSymbolAddress((void**)&wb,   g_wb);
    cudaGetSymbolAddress((void**)&bqkv, g_bqkv);

    __nv_bfloat16* rWqkv = wb;                       // q|k|v contiguous [3072,1024]
    __nv_bfloat16* rWo = wb + 3 * 1024 * 1024;
    __nv_bfloat16* rW1 = wb + 4 * 1024 * 1024;
    __nv_bfloat16* rW2 = wb + 8 * 1024 * 1024;

    const int SM3 = 3 * 2 * 128 * 72 * 2;            // 110592 bytes
    cudaFuncSetAttribute(tc_gemm<0>, cudaFuncAttributeMaxDynamicSharedMemorySize, SM3);
    cudaFuncSetAttribute(tc_gemm<2>, cudaFuncAttributeMaxDynamicSharedMemorySize, SM3);
    cudaFuncSetAttribute(tc_gemm<3>, cudaFuncAttributeMaxDynamicSharedMemorySize, SM3);
    cudaFuncSetAttribute(flash_kernel, cudaFuncAttributeMaxDynamicSharedMemorySize, FL_SMEM);

    dim3 blk(256);

    // 0: pack qkv bias
    pack_bias_kernel<<<12, blk>>>(bq, bk, bv, bqkv);
    // 1: convert Wq|Wk|Wv|Wo -> bf16
    round4_kernel<<<4096, blk>>>(Wq, Wk, Wv, Wo, rWqkv, rWqkv + 1024*1024,
                                 rWqkv + 2*1024*1024, rWo);
    // 2: h = LN1(x) -> bf16
    ln_kernel<<<TOK_, blk>>>(x, g1, be1, h);
    // 3: qkv = h @ [Wq|Wk|Wv]^T + b  (bf16 out)
    tc_gemm<0><<<dim3(QKVLD/128, TOK_/128), blk, SM3>>>(TOK_, QKVLD, HID_,
        h, HID_,  rWqkv, HID_,  nullptr, qkv, QKVLD,  bqkv, nullptr);
    // 4: vt = transpose(v)
    transpose_v_kernel<<<dim3(SS_/32, BB_*NH_*2), blk>>>(qkv, vt);
    // 5: fused attention -> ctx (bf16)
    flash_kernel<<<dim3(SS_/128, BB_*NH_), blk, FL_SMEM>>>(qkv, vt, am, ctx);
    // 6: convert W1|W2 -> bf16
    round2_kernel<<<8192, blk>>>(W1, W2, rW1, rW2);
    // 7: x2 = x + ctx @ Wo^T + bo  (fp32 out)
    tc_gemm<3><<<dim3(HID_/128, TOK_/128), blk, SM3>>>(TOK_, HID_, HID_,
        ctx, HID_,  rWo, HID_,  x2, nullptr, HID_,  bo, x);
    // 8: h2 = LN2(x2) -> bf16
    ln_kernel<<<TOK_, blk>>>(x2, g2, be2, h2);
    // 9: ff = gelu(h2 @ W1^T + b1)  (bf16 out)
    tc_gemm<2><<<dim3(FF_/128, TOK_/128), blk, SM3>>>(TOK_, FF_, HID_,
        h2, HID_,  rW1, HID_,  nullptr, ff, FF_,  b1, nullptr);
    // 10: out = x2 + ff @ W2^T + b2  (fp32 out)
    tc_gemm<3><<<dim3(HID_/128, TOK_/128), blk, SM3>>>(TOK_, HID_, FF_,
        ff, FF_,  rW2, FF_,  out, nullptr, HID_,  b2, x2);
}